// round 4
// baseline (speedup 1.0000x reference)
#include <cuda_runtime.h>
#include <cstdint>

#define NN 100000
#define EE 1600000

// ---------------- scratch (device globals; no allocations allowed) -------------
__device__ float g_deg[NN];
__device__ float g_dinv[NN];
__device__ float g_T[NN * 64];          // pre-propagate features (h @ W)
__device__ float g_H[4 * NN * 64];      // per-layer post-relu features
__device__ float g_M[64 * 64];          // Wq @ Wk^T
__device__ float g_scores[4 * NN];

// ---------------- degree / normalization ---------------------------------------
__global__ void k_initdeg(int n) {
    int i = blockIdx.x * 256 + threadIdx.x;
    if (i < n) g_deg[i] = 1.0f;  // self loop
}

__global__ void k_count(const int* __restrict__ ei, int E) {
    int e = blockIdx.x * 256 + threadIdx.x;
    if (e < E) atomicAdd(&g_deg[ei[E + e]], 1.0f);
}

__global__ void k_dinv(int n) {
    int i = blockIdx.x * 256 + threadIdx.x;
    if (i < n) g_dinv[i] = rsqrtf(g_deg[i]);
}

// ---------------- M = Wq @ Wk^T  (64x64) ----------------------------------------
__global__ void k_M(const float* __restrict__ Wq, const float* __restrict__ Wk) {
    int idx = blockIdx.x * 256 + threadIdx.x;   // 4096 total
    if (idx >= 64 * 64) return;
    int d = idx >> 6, j = idx & 63;
    float acc = 0.f;
#pragma unroll
    for (int e = 0; e < 64; e++) acc += Wq[d * 64 + e] * Wk[j * 64 + e];
    g_M[idx] = acc;
}

// ---------------- tall-skinny GEMM: g_T[n,64] = A[n,K] @ W[K,64] ----------------
// Also writes the self-loop term H[layer] = acc * dinv^2 in the epilogue.
// A is either external (srcLayer < 0) or g_H + srcLayer*n*64.
// BLOCK=256 threads. t = tid&15 owns 4 output cols; g = tid>>4 owns RPG rows.
template <int K, int RPG>
__global__ void __launch_bounds__(256) k_gemm(const float* __restrict__ Aext,
                                              int srcLayer, int dstLayer,
                                              const float* __restrict__ W,
                                              int nrows) {
    constexpr int ROWS = RPG * 16;
    __shared__ float shW[K * 64];
    __shared__ float shA[ROWS * K];
    int tid = threadIdx.x;

    const float* A = (srcLayer < 0) ? Aext : (g_H + (size_t)srcLayer * nrows * 64);

    // load W (K*16 float4)
    {
        const float4* W4 = (const float4*)W;
        float4* sW4 = (float4*)shW;
        for (int i = tid; i < K * 16; i += 256) sW4[i] = W4[i];
    }
    // load A tile
    int rowBase = blockIdx.x * ROWS;
    {
        float4* sA4 = (float4*)shA;
        const float4* A4 = (const float4*)A;
        const int q = K / 4;
        for (int i = tid; i < ROWS * q; i += 256) {
            int r = i / q;
            int row = rowBase + r;
            float4 v = make_float4(0.f, 0.f, 0.f, 0.f);
            if (row < nrows) v = A4[(size_t)row * q + (i - r * q)];
            sA4[i] = v;
        }
    }
    __syncthreads();

    int t = tid & 15, g = tid >> 4;
    float4 acc[RPG];
#pragma unroll
    for (int rr = 0; rr < RPG; rr++) acc[rr] = make_float4(0.f, 0.f, 0.f, 0.f);

#pragma unroll 4
    for (int k = 0; k < K; k += 4) {
        float4 w0 = *(const float4*)&shW[(k + 0) * 64 + t * 4];
        float4 w1 = *(const float4*)&shW[(k + 1) * 64 + t * 4];
        float4 w2 = *(const float4*)&shW[(k + 2) * 64 + t * 4];
        float4 w3 = *(const float4*)&shW[(k + 3) * 64 + t * 4];
#pragma unroll
        for (int rr = 0; rr < RPG; rr++) {
            float4 a4 = *(const float4*)&shA[(g * RPG + rr) * K + k];
            acc[rr].x = fmaf(a4.x, w0.x, acc[rr].x);
            acc[rr].y = fmaf(a4.x, w0.y, acc[rr].y);
            acc[rr].z = fmaf(a4.x, w0.z, acc[rr].z);
            acc[rr].w = fmaf(a4.x, w0.w, acc[rr].w);
            acc[rr].x = fmaf(a4.y, w1.x, acc[rr].x);
            acc[rr].y = fmaf(a4.y, w1.y, acc[rr].y);
            acc[rr].z = fmaf(a4.y, w1.z, acc[rr].z);
            acc[rr].w = fmaf(a4.y, w1.w, acc[rr].w);
            acc[rr].x = fmaf(a4.z, w2.x, acc[rr].x);
            acc[rr].y = fmaf(a4.z, w2.y, acc[rr].y);
            acc[rr].z = fmaf(a4.z, w2.z, acc[rr].z);
            acc[rr].w = fmaf(a4.z, w2.w, acc[rr].w);
            acc[rr].x = fmaf(a4.w, w3.x, acc[rr].x);
            acc[rr].y = fmaf(a4.w, w3.y, acc[rr].y);
            acc[rr].z = fmaf(a4.w, w3.z, acc[rr].z);
            acc[rr].w = fmaf(a4.w, w3.w, acc[rr].w);
        }
    }

    float* Hl = g_H + (size_t)dstLayer * nrows * 64;
#pragma unroll
    for (int rr = 0; rr < RPG; rr++) {
        int row = rowBase + g * RPG + rr;
        if (row < nrows) {
            ((float4*)g_T)[(size_t)row * 16 + t] = acc[rr];
            float dv = g_dinv[row];
            float d2 = dv * dv;
            float4 h = make_float4(acc[rr].x * d2, acc[rr].y * d2,
                                   acc[rr].z * d2, acc[rr].w * d2);
            ((float4*)Hl)[(size_t)row * 16 + t] = h;
        }
    }
}

// ---------------- edge scatter: H[l][dst] += T[src]*dinv[src]*dinv[dst] ----------
// 32 threads per edge, 2 floats per thread, scalar atomicAdd (-> REDG.ADD.F32).
__global__ void k_scatter(const int* __restrict__ ei, int E, int layer, int n) {
    int gid = blockIdx.x * 256 + threadIdx.x;
    int e = gid >> 5, lane = gid & 31;
    if (e >= E) return;
    int s = ei[e];
    int d = ei[E + e];
    float w = g_dinv[s] * g_dinv[d];
    float* Hl = g_H + (size_t)layer * n * 64;
    float v0 = g_T[(size_t)s * 64 + lane];
    float v1 = g_T[(size_t)s * 64 + lane + 32];
    atomicAdd(&Hl[(size_t)d * 64 + lane], v0 * w);
    atomicAdd(&Hl[(size_t)d * 64 + lane + 32], v1 * w);
}

// ---------------- bias + relu ----------------------------------------------------
__global__ void k_biasrelu(int layer, const float* __restrict__ b, int n) {
    int i = blockIdx.x * 256 + threadIdx.x;
    if (i < n * 64) {
        size_t o = (size_t)layer * n * 64 + i;
        g_H[o] = fmaxf(g_H[o] + b[i & 63], 0.f);
    }
}

// ---------------- scores: s[l,n] = (h^T M h) / TEMP ------------------------------
// warp per (layer,node) item, 16 items per warp per block pass.
__global__ void k_scores(int nitems) {
    __shared__ float shM[4096];
    __shared__ float shH[8][64];
    int tid = threadIdx.x;
    int w = tid >> 5, lane = tid & 31;
    for (int i = tid; i < 4096; i += 256) shM[i] = g_M[i];
    __syncthreads();
    int base = (blockIdx.x * 8 + w) * 16;
    for (int it = 0; it < 16; it++) {
        int item = base + it;
        if (item >= nitems) return;
        const float* h = g_H + (size_t)item * 64;
        shH[w][lane] = h[lane];
        shH[w][lane + 32] = h[lane + 32];
        __syncwarp();
        float a0 = 0.f, a1 = 0.f;
#pragma unroll
        for (int dd = 0; dd < 64; dd++) {
            float hd = shH[w][dd];
            a0 = fmaf(shM[dd * 64 + lane], hd, a0);
            a1 = fmaf(shM[dd * 64 + lane + 32], hd, a1);
        }
        float s = a0 * shH[w][lane] + a1 * shH[w][lane + 32];
#pragma unroll
        for (int off = 16; off; off >>= 1) s += __shfl_xor_sync(0xffffffffu, s, off);
        if (lane == 0) g_scores[item] = s * 10.0f;  // 1/TEMP
        __syncwarp();
    }
}

// ---------------- fused softmax + weighted sum + output GEMM ---------------------
// block = 128 threads handles 16 nodes.
__global__ void __launch_bounds__(128) k_final(const float* __restrict__ Wout,
                                               const float* __restrict__ bout,
                                               float* __restrict__ out, int n) {
    __shared__ float shW[64 * 40];
    __shared__ float shB[40];
    __shared__ float shS[16][64];
    int tid = threadIdx.x;
    for (int i = tid; i < 64 * 40; i += 128) shW[i] = Wout[i];
    if (tid < 40) shB[tid] = bout[tid];

    int nodeBase = blockIdx.x * 16;
    int nl = tid >> 3;      // local node 0..15
    int dg = tid & 7;       // 8 feats each
    int node = nodeBase + nl;
    if (node < n) {
        float s0 = g_scores[node];
        float s1 = g_scores[n + node];
        float s2 = g_scores[2 * n + node];
        float s3 = g_scores[3 * n + node];
        float m = fmaxf(fmaxf(s0, s1), fmaxf(s2, s3));
        float e0 = __expf(s0 - m), e1 = __expf(s1 - m);
        float e2 = __expf(s2 - m), e3 = __expf(s3 - m);
        float inv = 1.0f / (e0 + e1 + e2 + e3);
        e0 *= inv; e1 *= inv; e2 *= inv; e3 *= inv;
        size_t nh = (size_t)n * 64;
        size_t off0 = (size_t)node * 64 + dg * 8;
#pragma unroll
        for (int dd = 0; dd < 8; dd++) {
            size_t o = off0 + dd;
            float v = e0 * g_H[o] + e1 * g_H[nh + o] + e2 * g_H[2 * nh + o] + e3 * g_H[3 * nh + o];
            shS[nl][dg * 8 + dd] = v;
        }
    }
    __syncthreads();

    for (int o = tid; o < 16 * 40; o += 128) {
        int n2 = o / 40, c = o - n2 * 40;
        int node2 = nodeBase + n2;
        if (node2 < n) {
            float acc = shB[c];
#pragma unroll
            for (int k = 0; k < 64; k++) acc = fmaf(shS[n2][k], shW[k * 40 + c], acc);
            out[(size_t)node2 * 40 + c] = acc;
        }
    }
}

// ---------------- launch ---------------------------------------------------------
extern "C" void kernel_launch(void* const* d_in, const int* in_sizes, int n_in,
                              void* d_out, int out_size) {
    const float* x        = (const float*)d_in[0];
    const int*   ei       = (const int*)d_in[1];      // int32 on device (harness type set)
    const float* W0       = (const float*)d_in[2];
    const float* b0       = (const float*)d_in[3];
    const float* Ws       = (const float*)d_in[4];
    const float* bs       = (const float*)d_in[5];
    const float* Wq       = (const float*)d_in[6];
    const float* Wk       = (const float*)d_in[7];
    const float* Wout     = (const float*)d_in[8];
    const float* bout     = (const float*)d_in[9];
    float* out            = (float*)d_out;

    int n = in_sizes[0] / 128;
    int E = in_sizes[1] / 2;

    k_initdeg<<<(n + 255) / 256, 256>>>(n);
    k_count<<<(E + 255) / 256, 256>>>(ei, E);
    k_dinv<<<(n + 255) / 256, 256>>>(n);
    k_M<<<16, 256>>>(Wq, Wk);

    int elemBlocks = (n * 64 + 255) / 256;
    long long scatThreads = (long long)E * 32;
    int scatBlocks = (int)((scatThreads + 255) / 256);

    for (int l = 0; l < 4; l++) {
        if (l == 0) {
            k_gemm<128, 1><<<(n + 15) / 16, 256>>>(x, -1, 0, W0, n);
        } else {
            k_gemm<64, 4><<<(n + 63) / 64, 256>>>(nullptr, l - 1, l,
                                                  Ws + (size_t)(l - 1) * 64 * 64, n);
        }
        k_scatter<<<scatBlocks, 256>>>(ei, E, l, n);
        const float* b = (l == 0) ? b0 : (bs + (size_t)(l - 1) * 64);
        k_biasrelu<<<elemBlocks, 256>>>(l, b, n);
    }

    int nitems = 4 * n;
    k_scores<<<(nitems + 127) / 128, 256>>>(nitems);
    k_final<<<(n + 15) / 16, 128>>>(Wout, bout, out, n);
}

// round 5
// speedup vs baseline: 1.4297x; 1.4297x over previous
#include <cuda_runtime.h>
#include <cstdint>

#define NN 100000
#define EE 1600000

// ---------------- scratch (device globals; no allocations allowed) -------------
__device__ int   g_cnt[NN];            // in-degree (edges only)
__device__ int   g_rowptr[NN + 1];     // CSR row pointers (by dst)
__device__ int   g_cursor[NN];         // fill cursors
__device__ int   g_csrc[EE];           // CSR src indices
__device__ float g_dinv[NN];
__device__ float g_T[NN * 64];         // pre-propagate features (h @ W)
__device__ float g_H[4 * NN * 64];     // per-layer post-relu features
__device__ float g_M[64 * 64];         // Wq @ Wk^T
__device__ float g_scores[4 * NN];

// ---------------- degree / CSR build --------------------------------------------
__global__ void k_zerocnt(int n) {
    int i = blockIdx.x * 256 + threadIdx.x;
    if (i < n) g_cnt[i] = 0;
}

__global__ void k_count(const int* __restrict__ ei, int E) {
    int e = blockIdx.x * 256 + threadIdx.x;
    if (e < E) atomicAdd(&g_cnt[ei[E + e]], 1);
}

__global__ void k_dinv(int n) {
    int i = blockIdx.x * 256 + threadIdx.x;
    if (i < n) g_dinv[i] = rsqrtf((float)(g_cnt[i] + 1));  // +1 self loop
}

// single-block exclusive scan, 16 elements per thread
#define SCAN_T 1024
#define SCAN_C 16
__global__ void __launch_bounds__(SCAN_T) k_scan(int n) {
    __shared__ int sh[SCAN_T];
    __shared__ int s_carry;
    int tid = threadIdx.x;
    if (tid == 0) s_carry = 0;
    __syncthreads();
    const int CHUNK = SCAN_T * SCAN_C;
    for (int base = 0; base < n; base += CHUNK) {
        int local[SCAN_C];
        int sum = 0;
        int start = base + tid * SCAN_C;
#pragma unroll
        for (int k = 0; k < SCAN_C; k++) {
            int i = start + k;
            int v = (i < n) ? g_cnt[i] : 0;
            local[k] = sum;
            sum += v;
        }
        sh[tid] = sum;
        __syncthreads();
        for (int off = 1; off < SCAN_T; off <<= 1) {
            int t = (tid >= off) ? sh[tid - off] : 0;
            __syncthreads();
            sh[tid] += t;
            __syncthreads();
        }
        int excl = (tid ? sh[tid - 1] : 0) + s_carry;
#pragma unroll
        for (int k = 0; k < SCAN_C; k++) {
            int i = start + k;
            if (i < n) {
                int p = excl + local[k];
                g_rowptr[i] = p;
                g_cursor[i] = p;
            }
        }
        __syncthreads();
        if (tid == SCAN_T - 1) s_carry += sh[SCAN_T - 1];
        __syncthreads();
    }
    if (tid == 0) g_rowptr[n] = s_carry;
}

__global__ void k_fill(const int* __restrict__ ei, int E) {
    int e = blockIdx.x * 256 + threadIdx.x;
    if (e < E) {
        int s = ei[e];
        int d = ei[E + e];
        int pos = atomicAdd(&g_cursor[d], 1);
        g_csrc[pos] = s;
    }
}

// ---------------- M = Wq @ Wk^T  (64x64) ----------------------------------------
__global__ void k_M(const float* __restrict__ Wq, const float* __restrict__ Wk) {
    int idx = blockIdx.x * 256 + threadIdx.x;
    if (idx >= 64 * 64) return;
    int d = idx >> 6, j = idx & 63;
    float acc = 0.f;
#pragma unroll
    for (int e = 0; e < 64; e++) acc += Wq[d * 64 + e] * Wk[j * 64 + e];
    g_M[idx] = acc;
}

// ---------------- tall-skinny GEMM: g_T[n,64] = A[n,K] @ W[K,64] ----------------
// A is either external (srcLayer < 0) or g_H + srcLayer*n*64.
template <int K, int RPG>
__global__ void __launch_bounds__(256) k_gemm(const float* __restrict__ Aext,
                                              int srcLayer,
                                              const float* __restrict__ W,
                                              int nrows) {
    constexpr int ROWS = RPG * 16;
    __shared__ float shW[K * 64];
    __shared__ float shA[ROWS * K];
    int tid = threadIdx.x;

    const float* A = (srcLayer < 0) ? Aext : (g_H + (size_t)srcLayer * nrows * 64);

    {
        const float4* W4 = (const float4*)W;
        float4* sW4 = (float4*)shW;
        for (int i = tid; i < K * 16; i += 256) sW4[i] = W4[i];
    }
    int rowBase = blockIdx.x * ROWS;
    {
        float4* sA4 = (float4*)shA;
        const float4* A4 = (const float4*)A;
        const int q = K / 4;
        for (int i = tid; i < ROWS * q; i += 256) {
            int r = i / q;
            int row = rowBase + r;
            float4 v = make_float4(0.f, 0.f, 0.f, 0.f);
            if (row < nrows) v = A4[(size_t)row * q + (i - r * q)];
            sA4[i] = v;
        }
    }
    __syncthreads();

    int t = tid & 15, g = tid >> 4;
    float4 acc[RPG];
#pragma unroll
    for (int rr = 0; rr < RPG; rr++) acc[rr] = make_float4(0.f, 0.f, 0.f, 0.f);

#pragma unroll 4
    for (int k = 0; k < K; k += 4) {
        float4 w0 = *(const float4*)&shW[(k + 0) * 64 + t * 4];
        float4 w1 = *(const float4*)&shW[(k + 1) * 64 + t * 4];
        float4 w2 = *(const float4*)&shW[(k + 2) * 64 + t * 4];
        float4 w3 = *(const float4*)&shW[(k + 3) * 64 + t * 4];
#pragma unroll
        for (int rr = 0; rr < RPG; rr++) {
            float4 a4 = *(const float4*)&shA[(g * RPG + rr) * K + k];
            acc[rr].x = fmaf(a4.x, w0.x, acc[rr].x);
            acc[rr].y = fmaf(a4.x, w0.y, acc[rr].y);
            acc[rr].z = fmaf(a4.x, w0.z, acc[rr].z);
            acc[rr].w = fmaf(a4.x, w0.w, acc[rr].w);
            acc[rr].x = fmaf(a4.y, w1.x, acc[rr].x);
            acc[rr].y = fmaf(a4.y, w1.y, acc[rr].y);
            acc[rr].z = fmaf(a4.y, w1.z, acc[rr].z);
            acc[rr].w = fmaf(a4.y, w1.w, acc[rr].w);
            acc[rr].x = fmaf(a4.z, w2.x, acc[rr].x);
            acc[rr].y = fmaf(a4.z, w2.y, acc[rr].y);
            acc[rr].z = fmaf(a4.z, w2.z, acc[rr].z);
            acc[rr].w = fmaf(a4.z, w2.w, acc[rr].w);
            acc[rr].x = fmaf(a4.w, w3.x, acc[rr].x);
            acc[rr].y = fmaf(a4.w, w3.y, acc[rr].y);
            acc[rr].z = fmaf(a4.w, w3.z, acc[rr].z);
            acc[rr].w = fmaf(a4.w, w3.w, acc[rr].w);
        }
    }

#pragma unroll
    for (int rr = 0; rr < RPG; rr++) {
        int row = rowBase + g * RPG + rr;
        if (row < nrows) ((float4*)g_T)[(size_t)row * 16 + t] = acc[rr];
    }
}

// ---------------- CSR gather propagate + bias + relu, fused ----------------------
// one warp per dst node; lane owns feats {lane, lane+32}.
// H[l][d] = relu( dinv[d] * (T[d]*dinv[d] + sum_{s in N(d)} T[s]*dinv[s]) + b )
__global__ void __launch_bounds__(256) k_gather(int layer, const float* __restrict__ b,
                                                int n) {
    int warp = (blockIdx.x * 256 + threadIdx.x) >> 5;
    int lane = threadIdx.x & 31;
    if (warp >= n) return;
    int start = g_rowptr[warp];
    int end = g_rowptr[warp + 1];
    float dv = g_dinv[warp];
    float a0 = g_T[(size_t)warp * 64 + lane] * dv;
    float a1 = g_T[(size_t)warp * 64 + lane + 32] * dv;
    int j = start;
    for (; j + 4 <= end; j += 4) {
        int s0 = g_csrc[j], s1 = g_csrc[j + 1], s2 = g_csrc[j + 2], s3 = g_csrc[j + 3];
        float w0 = g_dinv[s0], w1 = g_dinv[s1], w2 = g_dinv[s2], w3 = g_dinv[s3];
        a0 = fmaf(g_T[(size_t)s0 * 64 + lane], w0, a0);
        a1 = fmaf(g_T[(size_t)s0 * 64 + lane + 32], w0, a1);
        a0 = fmaf(g_T[(size_t)s1 * 64 + lane], w1, a0);
        a1 = fmaf(g_T[(size_t)s1 * 64 + lane + 32], w1, a1);
        a0 = fmaf(g_T[(size_t)s2 * 64 + lane], w2, a0);
        a1 = fmaf(g_T[(size_t)s2 * 64 + lane + 32], w2, a1);
        a0 = fmaf(g_T[(size_t)s3 * 64 + lane], w3, a0);
        a1 = fmaf(g_T[(size_t)s3 * 64 + lane + 32], w3, a1);
    }
    for (; j < end; j++) {
        int s = g_csrc[j];
        float w = g_dinv[s];
        a0 = fmaf(g_T[(size_t)s * 64 + lane], w, a0);
        a1 = fmaf(g_T[(size_t)s * 64 + lane + 32], w, a1);
    }
    size_t o = (size_t)layer * n * 64 + (size_t)warp * 64;
    g_H[o + lane] = fmaxf(fmaf(a0, dv, b[lane]), 0.f);
    g_H[o + lane + 32] = fmaxf(fmaf(a1, dv, b[lane + 32]), 0.f);
}

// ---------------- scores: s[l,n] = (h^T M h) / TEMP ------------------------------
__global__ void k_scores(int nitems) {
    __shared__ float shM[4096];
    __shared__ float shH[8][64];
    int tid = threadIdx.x;
    int w = tid >> 5, lane = tid & 31;
    for (int i = tid; i < 4096; i += 256) shM[i] = g_M[i];
    __syncthreads();
    int base = (blockIdx.x * 8 + w) * 16;
    for (int it = 0; it < 16; it++) {
        int item = base + it;
        if (item >= nitems) return;
        const float* h = g_H + (size_t)item * 64;
        shH[w][lane] = h[lane];
        shH[w][lane + 32] = h[lane + 32];
        __syncwarp();
        float a0 = 0.f, a1 = 0.f;
#pragma unroll
        for (int dd = 0; dd < 64; dd++) {
            float hd = shH[w][dd];
            a0 = fmaf(shM[dd * 64 + lane], hd, a0);
            a1 = fmaf(shM[dd * 64 + lane + 32], hd, a1);
        }
        float s = a0 * shH[w][lane] + a1 * shH[w][lane + 32];
#pragma unroll
        for (int off = 16; off; off >>= 1) s += __shfl_xor_sync(0xffffffffu, s, off);
        if (lane == 0) g_scores[item] = s * 10.0f;  // 1/TEMP
        __syncwarp();
    }
}

// ---------------- fused softmax + weighted sum + output GEMM ---------------------
__global__ void __launch_bounds__(128) k_final(const float* __restrict__ Wout,
                                               const float* __restrict__ bout,
                                               float* __restrict__ out, int n) {
    __shared__ float shW[64 * 40];
    __shared__ float shB[40];
    __shared__ float shS[16][64];
    int tid = threadIdx.x;
    for (int i = tid; i < 64 * 40; i += 128) shW[i] = Wout[i];
    if (tid < 40) shB[tid] = bout[tid];

    int nodeBase = blockIdx.x * 16;
    int nl = tid >> 3;
    int dg = tid & 7;
    int node = nodeBase + nl;
    if (node < n) {
        float s0 = g_scores[node];
        float s1 = g_scores[n + node];
        float s2 = g_scores[2 * n + node];
        float s3 = g_scores[3 * n + node];
        float m = fmaxf(fmaxf(s0, s1), fmaxf(s2, s3));
        float e0 = __expf(s0 - m), e1 = __expf(s1 - m);
        float e2 = __expf(s2 - m), e3 = __expf(s3 - m);
        float inv = 1.0f / (e0 + e1 + e2 + e3);
        e0 *= inv; e1 *= inv; e2 *= inv; e3 *= inv;
        size_t nh = (size_t)n * 64;
        size_t off0 = (size_t)node * 64 + dg * 8;
#pragma unroll
        for (int dd = 0; dd < 8; dd++) {
            size_t o = off0 + dd;
            float v = e0 * g_H[o] + e1 * g_H[nh + o] + e2 * g_H[2 * nh + o] + e3 * g_H[3 * nh + o];
            shS[nl][dg * 8 + dd] = v;
        }
    }
    __syncthreads();

    for (int o = tid; o < 16 * 40; o += 128) {
        int n2 = o / 40, c = o - n2 * 40;
        int node2 = nodeBase + n2;
        if (node2 < n) {
            float acc = shB[c];
#pragma unroll
            for (int k = 0; k < 64; k++) acc = fmaf(shS[n2][k], shW[k * 40 + c], acc);
            out[(size_t)node2 * 40 + c] = acc;
        }
    }
}

// ---------------- launch ---------------------------------------------------------
extern "C" void kernel_launch(void* const* d_in, const int* in_sizes, int n_in,
                              void* d_out, int out_size) {
    const float* x    = (const float*)d_in[0];
    const int*   ei   = (const int*)d_in[1];   // int32 on device
    const float* W0   = (const float*)d_in[2];
    const float* b0   = (const float*)d_in[3];
    const float* Ws   = (const float*)d_in[4];
    const float* bs   = (const float*)d_in[5];
    const float* Wq   = (const float*)d_in[6];
    const float* Wk   = (const float*)d_in[7];
    const float* Wout = (const float*)d_in[8];
    const float* bout = (const float*)d_in[9];
    float* out        = (float*)d_out;

    int n = in_sizes[0] / 128;
    int E = in_sizes[1] / 2;

    // CSR build (per launch; graph-capturable)
    k_zerocnt<<<(n + 255) / 256, 256>>>(n);
    k_count<<<(E + 255) / 256, 256>>>(ei, E);
    k_dinv<<<(n + 255) / 256, 256>>>(n);
    k_scan<<<1, SCAN_T>>>(n);
    k_fill<<<(E + 255) / 256, 256>>>(ei, E);
    k_M<<<16, 256>>>(Wq, Wk);

    int gatherBlocks = (n * 32 + 255) / 256;

    for (int l = 0; l < 4; l++) {
        if (l == 0) {
            k_gemm<128, 1><<<(n + 15) / 16, 256>>>(x, -1, W0, n);
        } else {
            k_gemm<64, 4><<<(n + 63) / 64, 256>>>(nullptr, l - 1,
                                                  Ws + (size_t)(l - 1) * 64 * 64, n);
        }
        const float* b = (l == 0) ? b0 : (bs + (size_t)(l - 1) * 64);
        k_gather<<<gatherBlocks, 256>>>(l, b, n);
    }

    int nitems = 4 * n;
    k_scores<<<(nitems + 127) / 128, 256>>>(nitems);
    k_final<<<(n + 15) / 16, 128>>>(Wout, bout, out, n);
}

// round 6
// speedup vs baseline: 1.7424x; 1.2188x over previous
#include <cuda_runtime.h>
#include <cstdint>

#define NN 100000
#define EE 1600000
#define SCAN_BLK 2048          // elements per scan block (256 threads x 8)
#define MAX_PARTS 128

// ---------------- scratch (device globals; no allocations allowed) -------------
__device__ int   g_cnt[NN];            // in-degree (edges only)
__device__ int   g_rowptr[NN + 1];     // CSR row pointers (by dst)
__device__ int   g_cursor[NN];         // fill cursors
__device__ int   g_csrc[EE];           // CSR src indices
__device__ int   g_part[MAX_PARTS];    // scan partials
__device__ float g_dinv[NN];
__device__ float g_T[NN * 64];         // Ts = (h @ W) * dinv[row]
__device__ float g_H[4 * NN * 64];     // per-layer post-relu features
__device__ float g_M[64 * 64];         // Wq @ Wk^T
__device__ float g_scores[4 * NN];

// ---------------- degree / CSR build --------------------------------------------
__global__ void k_zerocnt(int n) {
    int i = blockIdx.x * 256 + threadIdx.x;
    if (i < n) g_cnt[i] = 0;
}

__global__ void k_count(const int* __restrict__ ei, int E) {
    int e = blockIdx.x * 256 + threadIdx.x;
    if (e < E) atomicAdd(&g_cnt[ei[E + e]], 1);
}

__global__ void k_dinv(int n) {
    int i = blockIdx.x * 256 + threadIdx.x;
    if (i < n) g_dinv[i] = rsqrtf((float)(g_cnt[i] + 1));  // +1 self loop
}

// ---- scan phase 1: per-block reduce (256 thr x 8 elems) -> g_part[blk] ----------
__global__ void __launch_bounds__(256) k_scan1(int n) {
    int tid = threadIdx.x;
    int base = blockIdx.x * SCAN_BLK + tid * 8;
    int s = 0;
#pragma unroll
    for (int k = 0; k < 8; k++) {
        int i = base + k;
        if (i < n) s += g_cnt[i];
    }
#pragma unroll
    for (int off = 16; off; off >>= 1) s += __shfl_xor_sync(0xffffffffu, s, off);
    __shared__ int sw[8];
    if ((tid & 31) == 0) sw[tid >> 5] = s;
    __syncthreads();
    if (tid == 0) {
        int t = 0;
#pragma unroll
        for (int w = 0; w < 8; w++) t += sw[w];
        g_part[blockIdx.x] = t;
    }
}

// ---- scan phase 2: exclusive scan of partials (single small block) --------------
__global__ void k_scan2(int nparts, int n) {
    __shared__ int sh[MAX_PARTS];
    int tid = threadIdx.x;
    sh[tid] = (tid < nparts) ? g_part[tid] : 0;
    __syncthreads();
    for (int off = 1; off < MAX_PARTS; off <<= 1) {
        int t = (tid >= off) ? sh[tid - off] : 0;
        __syncthreads();
        sh[tid] += t;
        __syncthreads();
    }
    if (tid < nparts) g_part[tid] = (tid ? sh[tid - 1] : 0);
    if (tid == MAX_PARTS - 1) g_rowptr[n] = sh[MAX_PARTS - 1];
}

// ---- scan phase 3: block-local exclusive scan + offset -> rowptr/cursor ---------
__global__ void __launch_bounds__(256) k_scan3(int n) {
    __shared__ int sw[8];
    int tid = threadIdx.x;
    int base = blockIdx.x * SCAN_BLK + tid * 8;
    int v[8];
    int s = 0;
#pragma unroll
    for (int k = 0; k < 8; k++) {
        int i = base + k;
        int c = (i < n) ? g_cnt[i] : 0;
        v[k] = s;          // exclusive within thread
        s += c;
    }
    // warp inclusive scan of s
    int lane = tid & 31, w = tid >> 5;
    int incl = s;
#pragma unroll
    for (int off = 1; off < 32; off <<= 1) {
        int t = __shfl_up_sync(0xffffffffu, incl, off);
        if (lane >= off) incl += t;
    }
    if (lane == 31) sw[w] = incl;
    __syncthreads();
    int wofs = 0;
    if (tid < 8) {
        int t = sw[tid];
        int e = 0;
        for (int k = 0; k < 8; k++) { int tv = __shfl_sync(0xffu, t, k); if (k < tid) e += tv; }
        sw[tid] = e;
        (void)e;
    }
    __syncthreads();
    wofs = sw[w];
    int texcl = wofs + incl - s;                 // exclusive across block
    int blkofs = g_part[blockIdx.x];
#pragma unroll
    for (int k = 0; k < 8; k++) {
        int i = base + k;
        if (i < n) {
            int p = blkofs + texcl + v[k];
            g_rowptr[i] = p;
            g_cursor[i] = p;
        }
    }
}

__global__ void k_fill(const int* __restrict__ ei, int E) {
    int e = blockIdx.x * 256 + threadIdx.x;
    if (e < E) {
        int s = ei[e];
        int d = ei[E + e];
        int pos = atomicAdd(&g_cursor[d], 1);
        g_csrc[pos] = s;
    }
}

// ---------------- M = Wq @ Wk^T  (64x64), SMEM-staged ----------------------------
__global__ void __launch_bounds__(1024) k_M(const float* __restrict__ Wq,
                                            const float* __restrict__ Wk) {
    __shared__ float sq[64 * 64];
    __shared__ float sk[64 * 64];
    int tid = threadIdx.x;
    for (int i = tid; i < 4096; i += 1024) { sq[i] = Wq[i]; sk[i] = Wk[i]; }
    __syncthreads();
    int idx = blockIdx.x * 1024 + tid;
    int d = idx >> 6, j = idx & 63;
    float acc = 0.f;
#pragma unroll
    for (int e = 0; e < 64; e++) acc = fmaf(sq[d * 64 + e], sk[j * 64 + e], acc);
    g_M[idx] = acc;
}

// ---------------- tall-skinny GEMM: g_T[n,64] = (A[n,K] @ W[K,64]) * dinv[row] ---
template <int K, int RPG>
__global__ void __launch_bounds__(256) k_gemm(const float* __restrict__ Aext,
                                              int srcLayer,
                                              const float* __restrict__ W,
                                              int nrows) {
    constexpr int ROWS = RPG * 16;
    __shared__ float shW[K * 64];
    __shared__ float shA[ROWS * K];
    int tid = threadIdx.x;

    const float* A = (srcLayer < 0) ? Aext : (g_H + (size_t)srcLayer * nrows * 64);

    {
        const float4* W4 = (const float4*)W;
        float4* sW4 = (float4*)shW;
        for (int i = tid; i < K * 16; i += 256) sW4[i] = W4[i];
    }
    int rowBase = blockIdx.x * ROWS;
    {
        float4* sA4 = (float4*)shA;
        const float4* A4 = (const float4*)A;
        const int q = K / 4;
        for (int i = tid; i < ROWS * q; i += 256) {
            int r = i / q;
            int row = rowBase + r;
            float4 v = make_float4(0.f, 0.f, 0.f, 0.f);
            if (row < nrows) v = A4[(size_t)row * q + (i - r * q)];
            sA4[i] = v;
        }
    }
    __syncthreads();

    int t = tid & 15, g = tid >> 4;
    float4 acc[RPG];
#pragma unroll
    for (int rr = 0; rr < RPG; rr++) acc[rr] = make_float4(0.f, 0.f, 0.f, 0.f);

#pragma unroll 4
    for (int k = 0; k < K; k += 4) {
        float4 w0 = *(const float4*)&shW[(k + 0) * 64 + t * 4];
        float4 w1 = *(const float4*)&shW[(k + 1) * 64 + t * 4];
        float4 w2 = *(const float4*)&shW[(k + 2) * 64 + t * 4];
        float4 w3 = *(const float4*)&shW[(k + 3) * 64 + t * 4];
#pragma unroll
        for (int rr = 0; rr < RPG; rr++) {
            float4 a4 = *(const float4*)&shA[(g * RPG + rr) * K + k];
            acc[rr].x = fmaf(a4.x, w0.x, acc[rr].x);
            acc[rr].y = fmaf(a4.x, w0.y, acc[rr].y);
            acc[rr].z = fmaf(a4.x, w0.z, acc[rr].z);
            acc[rr].w = fmaf(a4.x, w0.w, acc[rr].w);
            acc[rr].x = fmaf(a4.y, w1.x, acc[rr].x);
            acc[rr].y = fmaf(a4.y, w1.y, acc[rr].y);
            acc[rr].z = fmaf(a4.y, w1.z, acc[rr].z);
            acc[rr].w = fmaf(a4.y, w1.w, acc[rr].w);
            acc[rr].x = fmaf(a4.z, w2.x, acc[rr].x);
            acc[rr].y = fmaf(a4.z, w2.y, acc[rr].y);
            acc[rr].z = fmaf(a4.z, w2.z, acc[rr].z);
            acc[rr].w = fmaf(a4.z, w2.w, acc[rr].w);
            acc[rr].x = fmaf(a4.w, w3.x, acc[rr].x);
            acc[rr].y = fmaf(a4.w, w3.y, acc[rr].y);
            acc[rr].z = fmaf(a4.w, w3.z, acc[rr].z);
            acc[rr].w = fmaf(a4.w, w3.w, acc[rr].w);
        }
    }

#pragma unroll
    for (int rr = 0; rr < RPG; rr++) {
        int row = rowBase + g * RPG + rr;
        if (row < nrows) {
            float dv = g_dinv[row];
            float4 v = make_float4(acc[rr].x * dv, acc[rr].y * dv,
                                   acc[rr].z * dv, acc[rr].w * dv);
            ((float4*)g_T)[(size_t)row * 16 + t] = v;
        }
    }
}

// ---------------- CSR gather propagate + bias + relu, fused ----------------------
// one warp per dst node; lane owns float2 at feat 2*lane.
// H[l][d] = relu( dinv[d] * (Ts[d] + sum_{s in N(d)} Ts[s]) + b )
__global__ void __launch_bounds__(256) k_gather(int layer, const float* __restrict__ b,
                                                int n) {
    int warp = (blockIdx.x * 256 + threadIdx.x) >> 5;
    int lane = threadIdx.x & 31;
    if (warp >= n) return;
    int start = g_rowptr[warp];
    int end = g_rowptr[warp + 1];
    const float2* T2 = (const float2*)g_T;
    float2 a = T2[(size_t)warp * 32 + lane];      // Ts[d]
    int j = start;
    for (; j + 8 <= end; j += 8) {
        int s0 = g_csrc[j],     s1 = g_csrc[j + 1], s2 = g_csrc[j + 2], s3 = g_csrc[j + 3];
        int s4 = g_csrc[j + 4], s5 = g_csrc[j + 5], s6 = g_csrc[j + 6], s7 = g_csrc[j + 7];
        float2 v0 = T2[(size_t)s0 * 32 + lane];
        float2 v1 = T2[(size_t)s1 * 32 + lane];
        float2 v2 = T2[(size_t)s2 * 32 + lane];
        float2 v3 = T2[(size_t)s3 * 32 + lane];
        float2 v4 = T2[(size_t)s4 * 32 + lane];
        float2 v5 = T2[(size_t)s5 * 32 + lane];
        float2 v6 = T2[(size_t)s6 * 32 + lane];
        float2 v7 = T2[(size_t)s7 * 32 + lane];
        a.x += ((v0.x + v1.x) + (v2.x + v3.x)) + ((v4.x + v5.x) + (v6.x + v7.x));
        a.y += ((v0.y + v1.y) + (v2.y + v3.y)) + ((v4.y + v5.y) + (v6.y + v7.y));
    }
    for (; j < end; j++) {
        int s = g_csrc[j];
        float2 v = T2[(size_t)s * 32 + lane];
        a.x += v.x;
        a.y += v.y;
    }
    float dv = g_dinv[warp];
    float2 bb = ((const float2*)b)[lane];
    float2 h;
    h.x = fmaxf(fmaf(a.x, dv, bb.x), 0.f);
    h.y = fmaxf(fmaf(a.y, dv, bb.y), 0.f);
    ((float2*)g_H)[(size_t)layer * n * 32 + (size_t)warp * 32 + lane] = h;
}

// ---------------- scores: s[l,n] = (h^T M h) / TEMP ------------------------------
__global__ void k_scores(int nitems) {
    __shared__ float shM[4096];
    __shared__ float shH[8][64];
    int tid = threadIdx.x;
    int w = tid >> 5, lane = tid & 31;
    for (int i = tid; i < 4096; i += 256) shM[i] = g_M[i];
    __syncthreads();
    int base = (blockIdx.x * 8 + w) * 16;
    for (int it = 0; it < 16; it++) {
        int item = base + it;
        if (item >= nitems) return;
        const float* h = g_H + (size_t)item * 64;
        shH[w][lane] = h[lane];
        shH[w][lane + 32] = h[lane + 32];
        __syncwarp();
        float a0 = 0.f, a1 = 0.f;
#pragma unroll
        for (int dd = 0; dd < 64; dd++) {
            float hd = shH[w][dd];
            a0 = fmaf(shM[dd * 64 + lane], hd, a0);
            a1 = fmaf(shM[dd * 64 + lane + 32], hd, a1);
        }
        float s = a0 * shH[w][lane] + a1 * shH[w][lane + 32];
#pragma unroll
        for (int off = 16; off; off >>= 1) s += __shfl_xor_sync(0xffffffffu, s, off);
        if (lane == 0) g_scores[item] = s * 10.0f;  // 1/TEMP
        __syncwarp();
    }
}

// ---------------- fused softmax + weighted sum + output GEMM ---------------------
__global__ void __launch_bounds__(128) k_final(const float* __restrict__ Wout,
                                               const float* __restrict__ bout,
                                               float* __restrict__ out, int n) {
    __shared__ float shW[64 * 40];
    __shared__ float shB[40];
    __shared__ float shS[16][64];
    int tid = threadIdx.x;
    for (int i = tid; i < 64 * 40; i += 128) shW[i] = Wout[i];
    if (tid < 40) shB[tid] = bout[tid];

    int nodeBase = blockIdx.x * 16;
    int nl = tid >> 3;
    int dg = tid & 7;
    int node = nodeBase + nl;
    if (node < n) {
        float s0 = g_scores[node];
        float s1 = g_scores[n + node];
        float s2 = g_scores[2 * n + node];
        float s3 = g_scores[3 * n + node];
        float m = fmaxf(fmaxf(s0, s1), fmaxf(s2, s3));
        float e0 = __expf(s0 - m), e1 = __expf(s1 - m);
        float e2 = __expf(s2 - m), e3 = __expf(s3 - m);
        float inv = 1.0f / (e0 + e1 + e2 + e3);
        e0 *= inv; e1 *= inv; e2 *= inv; e3 *= inv;
        size_t nh = (size_t)n * 64;
        size_t off0 = (size_t)node * 64 + dg * 8;
#pragma unroll
        for (int dd = 0; dd < 8; dd++) {
            size_t o = off0 + dd;
            float v = e0 * g_H[o] + e1 * g_H[nh + o] + e2 * g_H[2 * nh + o] + e3 * g_H[3 * nh + o];
            shS[nl][dg * 8 + dd] = v;
        }
    }
    __syncthreads();

    for (int o = tid; o < 16 * 40; o += 128) {
        int n2 = o / 40, c = o - n2 * 40;
        int node2 = nodeBase + n2;
        if (node2 < n) {
            float acc = shB[c];
#pragma unroll
            for (int k = 0; k < 64; k++) acc = fmaf(shS[n2][k], shW[k * 40 + c], acc);
            out[(size_t)node2 * 40 + c] = acc;
        }
    }
}

// ---------------- launch ---------------------------------------------------------
extern "C" void kernel_launch(void* const* d_in, const int* in_sizes, int n_in,
                              void* d_out, int out_size) {
    const float* x    = (const float*)d_in[0];
    const int*   ei   = (const int*)d_in[1];   // int32 on device
    const float* W0   = (const float*)d_in[2];
    const float* b0   = (const float*)d_in[3];
    const float* Ws   = (const float*)d_in[4];
    const float* bs   = (const float*)d_in[5];
    const float* Wq   = (const float*)d_in[6];
    const float* Wk   = (const float*)d_in[7];
    const float* Wout = (const float*)d_in[8];
    const float* bout = (const float*)d_in[9];
    float* out        = (float*)d_out;

    int n = in_sizes[0] / 128;
    int E = in_sizes[1] / 2;
    int nparts = (n + SCAN_BLK - 1) / SCAN_BLK;

    // CSR build (per launch; graph-capturable)
    k_zerocnt<<<(n + 255) / 256, 256>>>(n);
    k_count<<<(E + 255) / 256, 256>>>(ei, E);
    k_dinv<<<(n + 255) / 256, 256>>>(n);
    k_scan1<<<nparts, 256>>>(n);
    k_scan2<<<1, MAX_PARTS>>>(nparts, n);
    k_scan3<<<nparts, 256>>>(n);
    k_fill<<<(E + 255) / 256, 256>>>(ei, E);
    k_M<<<4, 1024>>>(Wq, Wk);

    int gatherBlocks = (n * 32 + 255) / 256;

    for (int l = 0; l < 4; l++) {
        if (l == 0) {
            k_gemm<128, 1><<<(n + 15) / 16, 256>>>(x, -1, W0, n);
        } else {
            k_gemm<64, 4><<<(n + 63) / 64, 256>>>(nullptr, l - 1,
                                                  Ws + (size_t)(l - 1) * 64 * 64, n);
        }
        const float* b = (l == 0) ? b0 : (bs + (size_t)(l - 1) * 64);
        k_gather<<<gatherBlocks, 256>>>(l, b, n);
    }

    int nitems = 4 * n;
    k_scores<<<(nitems + 127) / 128, 256>>>(nitems);
    k_final<<<(n + 15) / 16, 128>>>(Wout, bout, out, n);
}

// round 7
// speedup vs baseline: 2.1723x; 1.2467x over previous
#include <cuda_runtime.h>
#include <cstdint>

#define NN 100000
#define EE 1600000
#define SCAN_BLK 2048          // elements per scan block (256 threads x 8)
#define MAX_PARTS 128

// ---------------- scratch (device globals; no allocations allowed) -------------
__device__ int   g_cnt[NN];            // in-degree (edges only)
__device__ int   g_rowptr[NN + 1];     // CSR row pointers (by dst)
__device__ int   g_cursor[NN];         // fill cursors
__device__ int   g_csrc[EE];           // CSR src indices
__device__ int   g_part[MAX_PARTS];    // scan partials
__device__ float g_dinv[NN];
__device__ float g_T[NN * 64];         // Ts = (h @ W) * dinv[row]
__device__ float g_H[4 * NN * 64];     // per-layer post-relu features
__device__ float g_M[64 * 64];         // Wq @ Wk^T
__device__ float g_scores[4 * NN];

// ---------------- degree / CSR build --------------------------------------------
__global__ void k_zerocnt(int n) {
    int i = blockIdx.x * 256 + threadIdx.x;
    if (i < n) g_cnt[i] = 0;
}

__global__ void k_count(const int* __restrict__ ei, int E) {
    int e = blockIdx.x * 256 + threadIdx.x;
    if (e < E) atomicAdd(&g_cnt[ei[E + e]], 1);
}

__global__ void k_dinv(int n) {
    int i = blockIdx.x * 256 + threadIdx.x;
    if (i < n) g_dinv[i] = rsqrtf((float)(g_cnt[i] + 1));  // +1 self loop
}

// ---- scan phase 1: per-block reduce (256 thr x 8 elems) -> g_part[blk] ----------
__global__ void __launch_bounds__(256) k_scan1(int n) {
    int tid = threadIdx.x;
    int base = blockIdx.x * SCAN_BLK + tid * 8;
    int s = 0;
#pragma unroll
    for (int k = 0; k < 8; k++) {
        int i = base + k;
        if (i < n) s += g_cnt[i];
    }
#pragma unroll
    for (int off = 16; off; off >>= 1) s += __shfl_xor_sync(0xffffffffu, s, off);
    __shared__ int sw[8];
    if ((tid & 31) == 0) sw[tid >> 5] = s;
    __syncthreads();
    if (tid == 0) {
        int t = 0;
#pragma unroll
        for (int w = 0; w < 8; w++) t += sw[w];
        g_part[blockIdx.x] = t;
    }
}

// ---- scan phase 2: exclusive scan of partials (single small block) --------------
__global__ void k_scan2(int nparts, int n) {
    __shared__ int sh[MAX_PARTS];
    int tid = threadIdx.x;
    sh[tid] = (tid < nparts) ? g_part[tid] : 0;
    __syncthreads();
    for (int off = 1; off < MAX_PARTS; off <<= 1) {
        int t = (tid >= off) ? sh[tid - off] : 0;
        __syncthreads();
        sh[tid] += t;
        __syncthreads();
    }
    if (tid < nparts) g_part[tid] = (tid ? sh[tid - 1] : 0);
    if (tid == MAX_PARTS - 1) g_rowptr[n] = sh[MAX_PARTS - 1];
}

// ---- scan phase 3: block-local exclusive scan + offset -> rowptr/cursor ---------
__global__ void __launch_bounds__(256) k_scan3(int n) {
    __shared__ int sw[8];
    int tid = threadIdx.x;
    int base = blockIdx.x * SCAN_BLK + tid * 8;
    int v[8];
    int s = 0;
#pragma unroll
    for (int k = 0; k < 8; k++) {
        int i = base + k;
        int c = (i < n) ? g_cnt[i] : 0;
        v[k] = s;          // exclusive within thread
        s += c;
    }
    // warp inclusive scan of s
    int lane = tid & 31, w = tid >> 5;
    int incl = s;
#pragma unroll
    for (int off = 1; off < 32; off <<= 1) {
        int t = __shfl_up_sync(0xffffffffu, incl, off);
        if (lane >= off) incl += t;
    }
    if (lane == 31) sw[w] = incl;
    __syncthreads();
    int wofs = 0;
    if (tid < 8) {
        int t = sw[tid];
        int e = 0;
        for (int k = 0; k < 8; k++) { int tv = __shfl_sync(0xffu, t, k); if (k < tid) e += tv; }
        sw[tid] = e;
        (void)e;
    }
    __syncthreads();
    wofs = sw[w];
    int texcl = wofs + incl - s;                 // exclusive across block
    int blkofs = g_part[blockIdx.x];
#pragma unroll
    for (int k = 0; k < 8; k++) {
        int i = base + k;
        if (i < n) {
            int p = blkofs + texcl + v[k];
            g_rowptr[i] = p;
            g_cursor[i] = p;
        }
    }
}

__global__ void k_fill(const int* __restrict__ ei, int E) {
    int e = blockIdx.x * 256 + threadIdx.x;
    if (e < E) {
        int s = ei[e];
        int d = ei[E + e];
        int pos = atomicAdd(&g_cursor[d], 1);
        g_csrc[pos] = s;
    }
}

// ---------------- M = Wq @ Wk^T  (64x64), SMEM-staged ----------------------------
__global__ void __launch_bounds__(1024) k_M(const float* __restrict__ Wq,
                                            const float* __restrict__ Wk) {
    __shared__ float sq[64 * 64];
    __shared__ float sk[64 * 64];
    int tid = threadIdx.x;
    for (int i = tid; i < 4096; i += 1024) { sq[i] = Wq[i]; sk[i] = Wk[i]; }
    __syncthreads();
    int idx = blockIdx.x * 1024 + tid;
    int d = idx >> 6, j = idx & 63;
    float acc = 0.f;
#pragma unroll
    for (int e = 0; e < 64; e++) acc = fmaf(sq[d * 64 + e], sk[j * 64 + e], acc);
    g_M[idx] = acc;
}

// ---------------- tall-skinny GEMM: g_T[n,64] = (A[n,K] @ W[K,64]) * dinv[row] ---
template <int K, int RPG>
__global__ void __launch_bounds__(256) k_gemm(const float* __restrict__ Aext,
                                              int srcLayer,
                                              const float* __restrict__ W,
                                              int nrows) {
    constexpr int ROWS = RPG * 16;
    __shared__ float shW[K * 64];
    __shared__ float shA[ROWS * K];
    int tid = threadIdx.x;

    const float* A = (srcLayer < 0) ? Aext : (g_H + (size_t)srcLayer * nrows * 64);

    {
        const float4* W4 = (const float4*)W;
        float4* sW4 = (float4*)shW;
        for (int i = tid; i < K * 16; i += 256) sW4[i] = W4[i];
    }
    int rowBase = blockIdx.x * ROWS;
    {
        float4* sA4 = (float4*)shA;
        const float4* A4 = (const float4*)A;
        const int q = K / 4;
        for (int i = tid; i < ROWS * q; i += 256) {
            int r = i / q;
            int row = rowBase + r;
            float4 v = make_float4(0.f, 0.f, 0.f, 0.f);
            if (row < nrows) v = A4[(size_t)row * q + (i - r * q)];
            sA4[i] = v;
        }
    }
    __syncthreads();

    int t = tid & 15, g = tid >> 4;
    float4 acc[RPG];
#pragma unroll
    for (int rr = 0; rr < RPG; rr++) acc[rr] = make_float4(0.f, 0.f, 0.f, 0.f);

#pragma unroll 4
    for (int k = 0; k < K; k += 4) {
        float4 w0 = *(const float4*)&shW[(k + 0) * 64 + t * 4];
        float4 w1 = *(const float4*)&shW[(k + 1) * 64 + t * 4];
        float4 w2 = *(const float4*)&shW[(k + 2) * 64 + t * 4];
        float4 w3 = *(const float4*)&shW[(k + 3) * 64 + t * 4];
#pragma unroll
        for (int rr = 0; rr < RPG; rr++) {
            float4 a4 = *(const float4*)&shA[(g * RPG + rr) * K + k];
            acc[rr].x = fmaf(a4.x, w0.x, acc[rr].x);
            acc[rr].y = fmaf(a4.x, w0.y, acc[rr].y);
            acc[rr].z = fmaf(a4.x, w0.z, acc[rr].z);
            acc[rr].w = fmaf(a4.x, w0.w, acc[rr].w);
            acc[rr].x = fmaf(a4.y, w1.x, acc[rr].x);
            acc[rr].y = fmaf(a4.y, w1.y, acc[rr].y);
            acc[rr].z = fmaf(a4.y, w1.z, acc[rr].z);
            acc[rr].w = fmaf(a4.y, w1.w, acc[rr].w);
            acc[rr].x = fmaf(a4.z, w2.x, acc[rr].x);
            acc[rr].y = fmaf(a4.z, w2.y, acc[rr].y);
            acc[rr].z = fmaf(a4.z, w2.z, acc[rr].z);
            acc[rr].w = fmaf(a4.z, w2.w, acc[rr].w);
            acc[rr].x = fmaf(a4.w, w3.x, acc[rr].x);
            acc[rr].y = fmaf(a4.w, w3.y, acc[rr].y);
            acc[rr].z = fmaf(a4.w, w3.z, acc[rr].z);
            acc[rr].w = fmaf(a4.w, w3.w, acc[rr].w);
        }
    }

#pragma unroll
    for (int rr = 0; rr < RPG; rr++) {
        int row = rowBase + g * RPG + rr;
        if (row < nrows) {
            float dv = g_dinv[row];
            float4 v = make_float4(acc[rr].x * dv, acc[rr].y * dv,
                                   acc[rr].z * dv, acc[rr].w * dv);
            ((float4*)g_T)[(size_t)row * 16 + t] = v;
        }
    }
}

// ---------------- scores as GEMM + fused dot: s[row] = (H[row] @ M) . H[row] -----
// Same tiling as k_gemm<64,4>; epilogue dots P row against H row (still in shA)
// and reduces across the 16 t-threads via shfl.
__global__ void __launch_bounds__(256) k_score(int nitems) {
    constexpr int K = 64, RPG = 4, ROWS = 64;
    __shared__ float shW[K * 64];
    __shared__ float shA[ROWS * K];
    int tid = threadIdx.x;

    {
        float4* sW4 = (float4*)shW;
        const float4* M4 = (const float4*)g_M;
        for (int i = tid; i < K * 16; i += 256) sW4[i] = M4[i];
    }
    int rowBase = blockIdx.x * ROWS;
    {
        float4* sA4 = (float4*)shA;
        const float4* A4 = (const float4*)g_H;
        for (int i = tid; i < ROWS * 16; i += 256) {
            int r = i >> 4;
            int row = rowBase + r;
            float4 v = make_float4(0.f, 0.f, 0.f, 0.f);
            if (row < nitems) v = A4[(size_t)row * 16 + (i & 15)];
            sA4[i] = v;
        }
    }
    __syncthreads();

    int t = tid & 15, g = tid >> 4;
    float4 acc[RPG];
#pragma unroll
    for (int rr = 0; rr < RPG; rr++) acc[rr] = make_float4(0.f, 0.f, 0.f, 0.f);

#pragma unroll 4
    for (int k = 0; k < K; k += 4) {
        float4 w0 = *(const float4*)&shW[(k + 0) * 64 + t * 4];
        float4 w1 = *(const float4*)&shW[(k + 1) * 64 + t * 4];
        float4 w2 = *(const float4*)&shW[(k + 2) * 64 + t * 4];
        float4 w3 = *(const float4*)&shW[(k + 3) * 64 + t * 4];
#pragma unroll
        for (int rr = 0; rr < RPG; rr++) {
            float4 a4 = *(const float4*)&shA[(g * RPG + rr) * K + k];
            acc[rr].x = fmaf(a4.x, w0.x, acc[rr].x);
            acc[rr].y = fmaf(a4.x, w0.y, acc[rr].y);
            acc[rr].z = fmaf(a4.x, w0.z, acc[rr].z);
            acc[rr].w = fmaf(a4.x, w0.w, acc[rr].w);
            acc[rr].x = fmaf(a4.y, w1.x, acc[rr].x);
            acc[rr].y = fmaf(a4.y, w1.y, acc[rr].y);
            acc[rr].z = fmaf(a4.y, w1.z, acc[rr].z);
            acc[rr].w = fmaf(a4.y, w1.w, acc[rr].w);
            acc[rr].x = fmaf(a4.z, w2.x, acc[rr].x);
            acc[rr].y = fmaf(a4.z, w2.y, acc[rr].y);
            acc[rr].z = fmaf(a4.z, w2.z, acc[rr].z);
            acc[rr].w = fmaf(a4.z, w2.w, acc[rr].w);
            acc[rr].x = fmaf(a4.w, w3.x, acc[rr].x);
            acc[rr].y = fmaf(a4.w, w3.y, acc[rr].y);
            acc[rr].z = fmaf(a4.w, w3.z, acc[rr].z);
            acc[rr].w = fmaf(a4.w, w3.w, acc[rr].w);
        }
    }

    // epilogue: dot with own H row, reduce over 16 t-threads, scale by 1/TEMP
#pragma unroll
    for (int rr = 0; rr < RPG; rr++) {
        int row = rowBase + g * RPG + rr;
        float4 h4 = *(const float4*)&shA[(g * RPG + rr) * K + t * 4];
        float p = acc[rr].x * h4.x + acc[rr].y * h4.y
                + acc[rr].z * h4.z + acc[rr].w * h4.w;
        p += __shfl_xor_sync(0xffffffffu, p, 1);
        p += __shfl_xor_sync(0xffffffffu, p, 2);
        p += __shfl_xor_sync(0xffffffffu, p, 4);
        p += __shfl_xor_sync(0xffffffffu, p, 8);
        if (t == 0 && row < nitems) g_scores[row] = p * 10.0f;  // 1/TEMP
    }
}

// ---------------- CSR gather propagate + bias + relu, fused ----------------------
// one warp per dst node; lane owns float2 at feat 2*lane.
// H[l][d] = relu( dinv[d] * (Ts[d] + sum_{s in N(d)} Ts[s]) + b )
__global__ void __launch_bounds__(256) k_gather(int layer, const float* __restrict__ b,
                                                int n) {
    int warp = (blockIdx.x * 256 + threadIdx.x) >> 5;
    int lane = threadIdx.x & 31;
    if (warp >= n) return;
    int start = g_rowptr[warp];
    int end = g_rowptr[warp + 1];
    const float2* T2 = (const float2*)g_T;
    float2 a = T2[(size_t)warp * 32 + lane];      // Ts[d]
    int j = start;
    for (; j + 8 <= end; j += 8) {
        int s0 = g_csrc[j],     s1 = g_csrc[j + 1], s2 = g_csrc[j + 2], s3 = g_csrc[j + 3];
        int s4 = g_csrc[j + 4], s5 = g_csrc[j + 5], s6 = g_csrc[j + 6], s7 = g_csrc[j + 7];
        float2 v0 = T2[(size_t)s0 * 32 + lane];
        float2 v1 = T2[(size_t)s1 * 32 + lane];
        float2 v2 = T2[(size_t)s2 * 32 + lane];
        float2 v3 = T2[(size_t)s3 * 32 + lane];
        float2 v4 = T2[(size_t)s4 * 32 + lane];
        float2 v5 = T2[(size_t)s5 * 32 + lane];
        float2 v6 = T2[(size_t)s6 * 32 + lane];
        float2 v7 = T2[(size_t)s7 * 32 + lane];
        a.x += ((v0.x + v1.x) + (v2.x + v3.x)) + ((v4.x + v5.x) + (v6.x + v7.x));
        a.y += ((v0.y + v1.y) + (v2.y + v3.y)) + ((v4.y + v5.y) + (v6.y + v7.y));
    }
    for (; j < end; j++) {
        int s = g_csrc[j];
        float2 v = T2[(size_t)s * 32 + lane];
        a.x += v.x;
        a.y += v.y;
    }
    float dv = g_dinv[warp];
    float2 bb = ((const float2*)b)[lane];
    float2 h;
    h.x = fmaxf(fmaf(a.x, dv, bb.x), 0.f);
    h.y = fmaxf(fmaf(a.y, dv, bb.y), 0.f);
    ((float2*)g_H)[(size_t)layer * n * 32 + (size_t)warp * 32 + lane] = h;
}

// ---------------- fused softmax + weighted sum + output GEMM ---------------------
__global__ void __launch_bounds__(128) k_final(const float* __restrict__ Wout,
                                               const float* __restrict__ bout,
                                               float* __restrict__ out, int n) {
    __shared__ float shW[64 * 40];
    __shared__ float shB[40];
    __shared__ float shS[16][64];
    int tid = threadIdx.x;
    for (int i = tid; i < 64 * 40; i += 128) shW[i] = Wout[i];
    if (tid < 40) shB[tid] = bout[tid];

    int nodeBase = blockIdx.x * 16;
    int nl = tid >> 3;
    int dg = tid & 7;
    int node = nodeBase + nl;
    if (node < n) {
        float s0 = g_scores[node];
        float s1 = g_scores[n + node];
        float s2 = g_scores[2 * n + node];
        float s3 = g_scores[3 * n + node];
        float m = fmaxf(fmaxf(s0, s1), fmaxf(s2, s3));
        float e0 = __expf(s0 - m), e1 = __expf(s1 - m);
        float e2 = __expf(s2 - m), e3 = __expf(s3 - m);
        float inv = 1.0f / (e0 + e1 + e2 + e3);
        e0 *= inv; e1 *= inv; e2 *= inv; e3 *= inv;
        size_t nh = (size_t)n * 64;
        size_t off0 = (size_t)node * 64 + dg * 8;
#pragma unroll
        for (int dd = 0; dd < 8; dd++) {
            size_t o = off0 + dd;
            float v = e0 * g_H[o] + e1 * g_H[nh + o] + e2 * g_H[2 * nh + o] + e3 * g_H[3 * nh + o];
            shS[nl][dg * 8 + dd] = v;
        }
    }
    __syncthreads();

    for (int o = tid; o < 16 * 40; o += 128) {
        int n2 = o / 40, c = o - n2 * 40;
        int node2 = nodeBase + n2;
        if (node2 < n) {
            float acc = shB[c];
#pragma unroll
            for (int k = 0; k < 64; k++) acc = fmaf(shS[n2][k], shW[k * 40 + c], acc);
            out[(size_t)node2 * 40 + c] = acc;
        }
    }
}

// ---------------- launch ---------------------------------------------------------
extern "C" void kernel_launch(void* const* d_in, const int* in_sizes, int n_in,
                              void* d_out, int out_size) {
    const float* x    = (const float*)d_in[0];
    const int*   ei   = (const int*)d_in[1];   // int32 on device
    const float* W0   = (const float*)d_in[2];
    const float* b0   = (const float*)d_in[3];
    const float* Ws   = (const float*)d_in[4];
    const float* bs   = (const float*)d_in[5];
    const float* Wq   = (const float*)d_in[6];
    const float* Wk   = (const float*)d_in[7];
    const float* Wout = (const float*)d_in[8];
    const float* bout = (const float*)d_in[9];
    float* out        = (float*)d_out;

    int n = in_sizes[0] / 128;
    int E = in_sizes[1] / 2;
    int nparts = (n + SCAN_BLK - 1) / SCAN_BLK;

    // CSR build (per launch; graph-capturable)
    k_zerocnt<<<(n + 255) / 256, 256>>>(n);
    k_count<<<(E + 255) / 256, 256>>>(ei, E);
    k_dinv<<<(n + 255) / 256, 256>>>(n);
    k_scan1<<<nparts, 256>>>(n);
    k_scan2<<<1, MAX_PARTS>>>(nparts, n);
    k_scan3<<<nparts, 256>>>(n);
    k_fill<<<(E + 255) / 256, 256>>>(ei, E);
    k_M<<<4, 1024>>>(Wq, Wk);

    int gatherBlocks = (n * 32 + 255) / 256;

    for (int l = 0; l < 4; l++) {
        if (l == 0) {
            k_gemm<128, 1><<<(n + 15) / 16, 256>>>(x, -1, W0, n);
        } else {
            k_gemm<64, 4><<<(n + 63) / 64, 256>>>(nullptr, l - 1,
                                                  Ws + (size_t)(l - 1) * 64 * 64, n);
        }
        const float* b = (l == 0) ? b0 : (bs + (size_t)(l - 1) * 64);
        k_gather<<<gatherBlocks, 256>>>(l, b, n);
    }

    int nitems = 4 * n;
    k_score<<<(nitems + 63) / 64, 256>>>(nitems);
    k_final<<<(n + 15) / 16, 128>>>(Wout, bout, out, n);
}

// round 8
// speedup vs baseline: 2.3963x; 1.1031x over previous
#include <cuda_runtime.h>
#include <cstdint>

#define NN 100000
#define EE 1600000
#define SCAN_BLK 2048          // elements per scan block (256 threads x 8)
#define MAX_PARTS 128

// ---------------- scratch (device globals; no allocations allowed) -------------
__device__ int   g_cnt[NN];            // in-degree (edges only)
__device__ int   g_rowptr[NN + 1];     // CSR row pointers (by dst)
__device__ int   g_cursor[NN];         // fill cursors
__device__ int   g_csrc[EE];           // CSR src indices
__device__ int   g_part[MAX_PARTS];    // scan partials
__device__ float g_dinv[NN];
__device__ float g_T[NN * 64];         // Ts = (h @ W) * dinv[row]
__device__ float g_H[4 * NN * 64];     // per-layer post-relu features
__device__ float g_M[64 * 64];         // Wq @ Wk^T
__device__ float g_scores[4 * NN];

// ---------------- degree / CSR build --------------------------------------------
__global__ void k_zerocnt(int n) {
    int i = blockIdx.x * 256 + threadIdx.x;
    if (i < n) g_cnt[i] = 0;
}

__global__ void k_count(const int* __restrict__ ei, int E) {
    int e = blockIdx.x * 256 + threadIdx.x;
    if (e < E) atomicAdd(&g_cnt[ei[E + e]], 1);
}

// ---- scan phase 1: per-block reduce + dinv  -------------------------------------
__global__ void __launch_bounds__(256) k_scan1(int n) {
    int tid = threadIdx.x;
    int base = blockIdx.x * SCAN_BLK + tid * 8;
    int s = 0;
#pragma unroll
    for (int k = 0; k < 8; k++) {
        int i = base + k;
        if (i < n) {
            int c = g_cnt[i];
            s += c;
            g_dinv[i] = rsqrtf((float)(c + 1));   // +1 self loop
        }
    }
#pragma unroll
    for (int off = 16; off; off >>= 1) s += __shfl_xor_sync(0xffffffffu, s, off);
    __shared__ int sw[8];
    if ((tid & 31) == 0) sw[tid >> 5] = s;
    __syncthreads();
    if (tid == 0) {
        int t = 0;
#pragma unroll
        for (int w = 0; w < 8; w++) t += sw[w];
        g_part[blockIdx.x] = t;
    }
}

// ---- scan phase 2: exclusive scan of partials (single small block) --------------
__global__ void k_scan2(int nparts, int n) {
    __shared__ int sh[MAX_PARTS];
    int tid = threadIdx.x;
    sh[tid] = (tid < nparts) ? g_part[tid] : 0;
    __syncthreads();
    for (int off = 1; off < MAX_PARTS; off <<= 1) {
        int t = (tid >= off) ? sh[tid - off] : 0;
        __syncthreads();
        sh[tid] += t;
        __syncthreads();
    }
    if (tid < nparts) g_part[tid] = (tid ? sh[tid - 1] : 0);
    if (tid == MAX_PARTS - 1) g_rowptr[n] = sh[MAX_PARTS - 1];
}

// ---- scan phase 3: block-local exclusive scan + offset -> rowptr/cursor ---------
__global__ void __launch_bounds__(256) k_scan3(int n) {
    __shared__ int sw[8];
    int tid = threadIdx.x;
    int base = blockIdx.x * SCAN_BLK + tid * 8;
    int v[8];
    int s = 0;
#pragma unroll
    for (int k = 0; k < 8; k++) {
        int i = base + k;
        int c = (i < n) ? g_cnt[i] : 0;
        v[k] = s;          // exclusive within thread
        s += c;
    }
    int lane = tid & 31, w = tid >> 5;
    int incl = s;
#pragma unroll
    for (int off = 1; off < 32; off <<= 1) {
        int t = __shfl_up_sync(0xffffffffu, incl, off);
        if (lane >= off) incl += t;
    }
    if (lane == 31) sw[w] = incl;
    __syncthreads();
    int wofs = 0;
    if (tid < 8) {
        int t = sw[tid];
        int e = 0;
        for (int k = 0; k < 8; k++) { int tv = __shfl_sync(0xffu, t, k); if (k < tid) e += tv; }
        sw[tid] = e;
        (void)e;
    }
    __syncthreads();
    wofs = sw[w];
    int texcl = wofs + incl - s;                 // exclusive across block
    int blkofs = g_part[blockIdx.x];
#pragma unroll
    for (int k = 0; k < 8; k++) {
        int i = base + k;
        if (i < n) {
            int p = blkofs + texcl + v[k];
            g_rowptr[i] = p;
            g_cursor[i] = p;
        }
    }
}

__global__ void k_fill(const int* __restrict__ ei, int E) {
    int e = blockIdx.x * 256 + threadIdx.x;
    if (e < E) {
        int s = ei[e];
        int d = ei[E + e];
        int pos = atomicAdd(&g_cursor[d], 1);
        g_csrc[pos] = s;
    }
}

// ---------------- M = Wq @ Wk^T  (64x64), SMEM-staged ----------------------------
__global__ void __launch_bounds__(1024) k_M(const float* __restrict__ Wq,
                                            const float* __restrict__ Wk) {
    __shared__ float sq[64 * 64];
    __shared__ float sk[64 * 64];
    int tid = threadIdx.x;
    for (int i = tid; i < 4096; i += 1024) { sq[i] = Wq[i]; sk[i] = Wk[i]; }
    __syncthreads();
    int idx = blockIdx.x * 1024 + tid;
    int d = idx >> 6, j = idx & 63;
    float acc = 0.f;
#pragma unroll
    for (int e = 0; e < 64; e++) acc = fmaf(sq[d * 64 + e], sk[j * 64 + e], acc);
    g_M[idx] = acc;
}

// ---------------- tall-skinny GEMM: g_T[n,64] = (A[n,K] @ W[K,64]) * dinv[row] ---
template <int K, int RPG>
__global__ void __launch_bounds__(256) k_gemm(const float* __restrict__ Aext,
                                              int srcLayer,
                                              const float* __restrict__ W,
                                              int nrows) {
    constexpr int ROWS = RPG * 16;
    __shared__ float shW[K * 64];
    __shared__ float shA[ROWS * K];
    int tid = threadIdx.x;

    const float* A = (srcLayer < 0) ? Aext : (g_H + (size_t)srcLayer * nrows * 64);

    {
        const float4* W4 = (const float4*)W;
        float4* sW4 = (float4*)shW;
        for (int i = tid; i < K * 16; i += 256) sW4[i] = W4[i];
    }
    int rowBase = blockIdx.x * ROWS;
    {
        float4* sA4 = (float4*)shA;
        const float4* A4 = (const float4*)A;
        const int q = K / 4;
        for (int i = tid; i < ROWS * q; i += 256) {
            int r = i / q;
            int row = rowBase + r;
            float4 v = make_float4(0.f, 0.f, 0.f, 0.f);
            if (row < nrows) v = A4[(size_t)row * q + (i - r * q)];
            sA4[i] = v;
        }
    }
    __syncthreads();

    int t = tid & 15, g = tid >> 4;
    float4 acc[RPG];
#pragma unroll
    for (int rr = 0; rr < RPG; rr++) acc[rr] = make_float4(0.f, 0.f, 0.f, 0.f);

#pragma unroll 4
    for (int k = 0; k < K; k += 4) {
        float4 w0 = *(const float4*)&shW[(k + 0) * 64 + t * 4];
        float4 w1 = *(const float4*)&shW[(k + 1) * 64 + t * 4];
        float4 w2 = *(const float4*)&shW[(k + 2) * 64 + t * 4];
        float4 w3 = *(const float4*)&shW[(k + 3) * 64 + t * 4];
#pragma unroll
        for (int rr = 0; rr < RPG; rr++) {
            float4 a4 = *(const float4*)&shA[(g * RPG + rr) * K + k];
            acc[rr].x = fmaf(a4.x, w0.x, acc[rr].x);
            acc[rr].y = fmaf(a4.x, w0.y, acc[rr].y);
            acc[rr].z = fmaf(a4.x, w0.z, acc[rr].z);
            acc[rr].w = fmaf(a4.x, w0.w, acc[rr].w);
            acc[rr].x = fmaf(a4.y, w1.x, acc[rr].x);
            acc[rr].y = fmaf(a4.y, w1.y, acc[rr].y);
            acc[rr].z = fmaf(a4.y, w1.z, acc[rr].z);
            acc[rr].w = fmaf(a4.y, w1.w, acc[rr].w);
            acc[rr].x = fmaf(a4.z, w2.x, acc[rr].x);
            acc[rr].y = fmaf(a4.z, w2.y, acc[rr].y);
            acc[rr].z = fmaf(a4.z, w2.z, acc[rr].z);
            acc[rr].w = fmaf(a4.z, w2.w, acc[rr].w);
            acc[rr].x = fmaf(a4.w, w3.x, acc[rr].x);
            acc[rr].y = fmaf(a4.w, w3.y, acc[rr].y);
            acc[rr].z = fmaf(a4.w, w3.z, acc[rr].z);
            acc[rr].w = fmaf(a4.w, w3.w, acc[rr].w);
        }
    }

#pragma unroll
    for (int rr = 0; rr < RPG; rr++) {
        int row = rowBase + g * RPG + rr;
        if (row < nrows) {
            float dv = g_dinv[row];
            float4 v = make_float4(acc[rr].x * dv, acc[rr].y * dv,
                                   acc[rr].z * dv, acc[rr].w * dv);
            ((float4*)g_T)[(size_t)row * 16 + t] = v;
        }
    }
}

// ---------------- scores as GEMM + fused dot: s[row] = (H[row] @ M) . H[row] -----
__global__ void __launch_bounds__(256) k_score(int nitems) {
    constexpr int K = 64, RPG = 4, ROWS = 64;
    __shared__ float shW[K * 64];
    __shared__ float shA[ROWS * K];
    int tid = threadIdx.x;

    {
        float4* sW4 = (float4*)shW;
        const float4* M4 = (const float4*)g_M;
        for (int i = tid; i < K * 16; i += 256) sW4[i] = M4[i];
    }
    int rowBase = blockIdx.x * ROWS;
    {
        float4* sA4 = (float4*)shA;
        const float4* A4 = (const float4*)g_H;
        for (int i = tid; i < ROWS * 16; i += 256) {
            int r = i >> 4;
            int row = rowBase + r;
            float4 v = make_float4(0.f, 0.f, 0.f, 0.f);
            if (row < nitems) v = A4[(size_t)row * 16 + (i & 15)];
            sA4[i] = v;
        }
    }
    __syncthreads();

    int t = tid & 15, g = tid >> 4;
    float4 acc[RPG];
#pragma unroll
    for (int rr = 0; rr < RPG; rr++) acc[rr] = make_float4(0.f, 0.f, 0.f, 0.f);

#pragma unroll 4
    for (int k = 0; k < K; k += 4) {
        float4 w0 = *(const float4*)&shW[(k + 0) * 64 + t * 4];
        float4 w1 = *(const float4*)&shW[(k + 1) * 64 + t * 4];
        float4 w2 = *(const float4*)&shW[(k + 2) * 64 + t * 4];
        float4 w3 = *(const float4*)&shW[(k + 3) * 64 + t * 4];
#pragma unroll
        for (int rr = 0; rr < RPG; rr++) {
            float4 a4 = *(const float4*)&shA[(g * RPG + rr) * K + k];
            acc[rr].x = fmaf(a4.x, w0.x, acc[rr].x);
            acc[rr].y = fmaf(a4.x, w0.y, acc[rr].y);
            acc[rr].z = fmaf(a4.x, w0.z, acc[rr].z);
            acc[rr].w = fmaf(a4.x, w0.w, acc[rr].w);
            acc[rr].x = fmaf(a4.y, w1.x, acc[rr].x);
            acc[rr].y = fmaf(a4.y, w1.y, acc[rr].y);
            acc[rr].z = fmaf(a4.y, w1.z, acc[rr].z);
            acc[rr].w = fmaf(a4.y, w1.w, acc[rr].w);
            acc[rr].x = fmaf(a4.z, w2.x, acc[rr].x);
            acc[rr].y = fmaf(a4.z, w2.y, acc[rr].y);
            acc[rr].z = fmaf(a4.z, w2.z, acc[rr].z);
            acc[rr].w = fmaf(a4.z, w2.w, acc[rr].w);
            acc[rr].x = fmaf(a4.w, w3.x, acc[rr].x);
            acc[rr].y = fmaf(a4.w, w3.y, acc[rr].y);
            acc[rr].z = fmaf(a4.w, w3.z, acc[rr].z);
            acc[rr].w = fmaf(a4.w, w3.w, acc[rr].w);
        }
    }

#pragma unroll
    for (int rr = 0; rr < RPG; rr++) {
        int row = rowBase + g * RPG + rr;
        float4 h4 = *(const float4*)&shA[(g * RPG + rr) * K + t * 4];
        float p = acc[rr].x * h4.x + acc[rr].y * h4.y
                + acc[rr].z * h4.z + acc[rr].w * h4.w;
        p += __shfl_xor_sync(0xffffffffu, p, 1);
        p += __shfl_xor_sync(0xffffffffu, p, 2);
        p += __shfl_xor_sync(0xffffffffu, p, 4);
        p += __shfl_xor_sync(0xffffffffu, p, 8);
        if (t == 0 && row < nitems) g_scores[row] = p * 10.0f;  // 1/TEMP
    }
}

// ---------------- CSR gather propagate + bias + relu, fused ----------------------
__global__ void __launch_bounds__(256) k_gather(int layer, const float* __restrict__ b,
                                                int n) {
    int warp = (blockIdx.x * 256 + threadIdx.x) >> 5;
    int lane = threadIdx.x & 31;
    if (warp >= n) return;
    int start = g_rowptr[warp];
    int end = g_rowptr[warp + 1];
    const float2* T2 = (const float2*)g_T;
    float2 a = T2[(size_t)warp * 32 + lane];      // Ts[d]
    int j = start;
    for (; j + 8 <= end; j += 8) {
        int s0 = g_csrc[j],     s1 = g_csrc[j + 1], s2 = g_csrc[j + 2], s3 = g_csrc[j + 3];
        int s4 = g_csrc[j + 4], s5 = g_csrc[j + 5], s6 = g_csrc[j + 6], s7 = g_csrc[j + 7];
        float2 v0 = T2[(size_t)s0 * 32 + lane];
        float2 v1 = T2[(size_t)s1 * 32 + lane];
        float2 v2 = T2[(size_t)s2 * 32 + lane];
        float2 v3 = T2[(size_t)s3 * 32 + lane];
        float2 v4 = T2[(size_t)s4 * 32 + lane];
        float2 v5 = T2[(size_t)s5 * 32 + lane];
        float2 v6 = T2[(size_t)s6 * 32 + lane];
        float2 v7 = T2[(size_t)s7 * 32 + lane];
        a.x += ((v0.x + v1.x) + (v2.x + v3.x)) + ((v4.x + v5.x) + (v6.x + v7.x));
        a.y += ((v0.y + v1.y) + (v2.y + v3.y)) + ((v4.y + v5.y) + (v6.y + v7.y));
    }
    for (; j < end; j++) {
        int s = g_csrc[j];
        float2 v = T2[(size_t)s * 32 + lane];
        a.x += v.x;
        a.y += v.y;
    }
    float dv = g_dinv[warp];
    float2 bb = ((const float2*)b)[lane];
    float2 h;
    h.x = fmaxf(fmaf(a.x, dv, bb.x), 0.f);
    h.y = fmaxf(fmaf(a.y, dv, bb.y), 0.f);
    ((float2*)g_H)[(size_t)layer * n * 32 + (size_t)warp * 32 + lane] = h;
}

// ---------------- fused softmax + weighted sum + output GEMM ---------------------
__global__ void __launch_bounds__(128) k_final(const float* __restrict__ Wout,
                                               const float* __restrict__ bout,
                                               float* __restrict__ out, int n) {
    __shared__ float shW[64 * 40];
    __shared__ float shB[40];
    __shared__ float shS[16][64];
    int tid = threadIdx.x;
    for (int i = tid; i < 64 * 40; i += 128) shW[i] = Wout[i];
    if (tid < 40) shB[tid] = bout[tid];

    int nodeBase = blockIdx.x * 16;
    int nl = tid >> 3;
    int dg = tid & 7;
    int node = nodeBase + nl;
    if (node < n) {
        float s0 = g_scores[node];
        float s1 = g_scores[n + node];
        float s2 = g_scores[2 * n + node];
        float s3 = g_scores[3 * n + node];
        float m = fmaxf(fmaxf(s0, s1), fmaxf(s2, s3));
        float e0 = __expf(s0 - m), e1 = __expf(s1 - m);
        float e2 = __expf(s2 - m), e3 = __expf(s3 - m);
        float inv = 1.0f / (e0 + e1 + e2 + e3);
        e0 *= inv; e1 *= inv; e2 *= inv; e3 *= inv;
        size_t nh = (size_t)n * 64;
        size_t off0 = (size_t)node * 64 + dg * 8;
#pragma unroll
        for (int dd = 0; dd < 8; dd++) {
            size_t o = off0 + dd;
            float v = e0 * g_H[o] + e1 * g_H[nh + o] + e2 * g_H[2 * nh + o] + e3 * g_H[3 * nh + o];
            shS[nl][dg * 8 + dd] = v;
        }
    }
    __syncthreads();

    for (int o = tid; o < 16 * 40; o += 128) {
        int n2 = o / 40, c = o - n2 * 40;
        int node2 = nodeBase + n2;
        if (node2 < n) {
            float acc = shB[c];
#pragma unroll
            for (int k = 0; k < 64; k++) acc = fmaf(shS[n2][k], shW[k * 40 + c], acc);
            out[(size_t)node2 * 40 + c] = acc;
        }
    }
}

// ---------------- launch ---------------------------------------------------------
extern "C" void kernel_launch(void* const* d_in, const int* in_sizes, int n_in,
                              void* d_out, int out_size) {
    const float* x    = (const float*)d_in[0];
    const int*   ei   = (const int*)d_in[1];   // int32 on device
    const float* W0   = (const float*)d_in[2];
    const float* b0   = (const float*)d_in[3];
    const float* Ws   = (const float*)d_in[4];
    const float* bs   = (const float*)d_in[5];
    const float* Wq   = (const float*)d_in[6];
    const float* Wk   = (const float*)d_in[7];
    const float* Wout = (const float*)d_in[8];
    const float* bout = (const float*)d_in[9];
    float* out        = (float*)d_out;

    int n = in_sizes[0] / 128;
    int E = in_sizes[1] / 2;
    int nparts = (n + SCAN_BLK - 1) / SCAN_BLK;

    // launch order arranged so launch #5 (ncu -s 5 -c 1) is the K=128 GEMM
    k_zerocnt<<<(n + 255) / 256, 256>>>(n);            // 0
    k_count<<<(E + 255) / 256, 256>>>(ei, E);          // 1
    k_scan1<<<nparts, 256>>>(n);                       // 2 (also writes dinv)
    k_scan2<<<1, MAX_PARTS>>>(nparts, n);              // 3
    k_scan3<<<nparts, 256>>>(n);                       // 4
    k_gemm<128, 4><<<(n + 63) / 64, 256>>>(x, -1, W0, n);   // 5  <- profiled
    k_fill<<<(E + 255) / 256, 256>>>(ei, E);           // 6
    k_M<<<4, 1024>>>(Wq, Wk);                          // 7

    int gatherBlocks = (n * 32 + 255) / 256;

    for (int l = 0; l < 4; l++) {
        if (l > 0) {
            k_gemm<64, 4><<<(n + 63) / 64, 256>>>(nullptr, l - 1,
                                                  Ws + (size_t)(l - 1) * 64 * 64, n);
        }
        const float* b = (l == 0) ? b0 : (bs + (size_t)(l - 1) * 64);
        k_gather<<<gatherBlocks, 256>>>(l, b, n);
    }

    int nitems = 4 * n;
    k_score<<<(nitems + 63) / 64, 256>>>(nitems);
    k_final<<<(n + 15) / 16, 128>>>(Wout, bout, out, n);
}

// round 9
// speedup vs baseline: 2.4081x; 1.0049x over previous
#include <cuda_runtime.h>
#include <cstdint>

#define NN 100000
#define EE 1600000
#define SCAN_BLK 2048          // elements per scan block (256 threads x 8)
#define MAX_PARTS 128

// ---------------- scratch (device globals; no allocations allowed) -------------
__device__ int   g_cnt[NN];            // in-degree (edges only)
__device__ int   g_rowptr[NN + 1];     // CSR row pointers (by dst)
__device__ int   g_cursor[NN];         // fill cursors
__device__ int   g_csrc[EE];           // CSR src indices
__device__ int   g_part[MAX_PARTS];    // scan partials
__device__ float g_dinv[NN];
__device__ float g_T[NN * 64];         // Ts = (h @ W) * dinv[row]
__device__ float g_H[4 * NN * 64];     // per-layer post-relu features
__device__ float g_M[64 * 64];         // Wq @ Wk^T
__device__ float g_scores[4 * NN];

// ---------------- degree / CSR build --------------------------------------------
__global__ void k_zerocnt(int n) {
    int i = blockIdx.x * 256 + threadIdx.x;
    if (i < n) g_cnt[i] = 0;
}

__global__ void k_count(const int* __restrict__ ei, int E) {
    int e = blockIdx.x * 256 + threadIdx.x;
    if (e < E) atomicAdd(&g_cnt[ei[E + e]], 1);
}

// ---- scan phase 1: per-block reduce + dinv  -------------------------------------
__global__ void __launch_bounds__(256) k_scan1(int n) {
    int tid = threadIdx.x;
    int base = blockIdx.x * SCAN_BLK + tid * 8;
    int s = 0;
#pragma unroll
    for (int k = 0; k < 8; k++) {
        int i = base + k;
        if (i < n) {
            int c = g_cnt[i];
            s += c;
            g_dinv[i] = rsqrtf((float)(c + 1));   // +1 self loop
        }
    }
#pragma unroll
    for (int off = 16; off; off >>= 1) s += __shfl_xor_sync(0xffffffffu, s, off);
    __shared__ int sw[8];
    if ((tid & 31) == 0) sw[tid >> 5] = s;
    __syncthreads();
    if (tid == 0) {
        int t = 0;
#pragma unroll
        for (int w = 0; w < 8; w++) t += sw[w];
        g_part[blockIdx.x] = t;
    }
}

// ---- scan phase 2: exclusive scan of partials (single small block) --------------
__global__ void k_scan2(int nparts, int n) {
    __shared__ int sh[MAX_PARTS];
    int tid = threadIdx.x;
    sh[tid] = (tid < nparts) ? g_part[tid] : 0;
    __syncthreads();
    for (int off = 1; off < MAX_PARTS; off <<= 1) {
        int t = (tid >= off) ? sh[tid - off] : 0;
        __syncthreads();
        sh[tid] += t;
        __syncthreads();
    }
    if (tid < nparts) g_part[tid] = (tid ? sh[tid - 1] : 0);
    if (tid == MAX_PARTS - 1) g_rowptr[n] = sh[MAX_PARTS - 1];
}

// ---- scan phase 3: block-local exclusive scan + offset -> rowptr/cursor ---------
__global__ void __launch_bounds__(256) k_scan3(int n) {
    __shared__ int sw[8];
    int tid = threadIdx.x;
    int base = blockIdx.x * SCAN_BLK + tid * 8;
    int v[8];
    int s = 0;
#pragma unroll
    for (int k = 0; k < 8; k++) {
        int i = base + k;
        int c = (i < n) ? g_cnt[i] : 0;
        v[k] = s;          // exclusive within thread
        s += c;
    }
    int lane = tid & 31, w = tid >> 5;
    int incl = s;
#pragma unroll
    for (int off = 1; off < 32; off <<= 1) {
        int t = __shfl_up_sync(0xffffffffu, incl, off);
        if (lane >= off) incl += t;
    }
    if (lane == 31) sw[w] = incl;
    __syncthreads();
    int wofs = 0;
    if (tid < 8) {
        int t = sw[tid];
        int e = 0;
        for (int k = 0; k < 8; k++) { int tv = __shfl_sync(0xffu, t, k); if (k < tid) e += tv; }
        sw[tid] = e;
        (void)e;
    }
    __syncthreads();
    wofs = sw[w];
    int texcl = wofs + incl - s;                 // exclusive across block
    int blkofs = g_part[blockIdx.x];
#pragma unroll
    for (int k = 0; k < 8; k++) {
        int i = base + k;
        if (i < n) {
            int p = blkofs + texcl + v[k];
            g_rowptr[i] = p;
            g_cursor[i] = p;
        }
    }
}

__global__ void k_fill(const int* __restrict__ ei, int E) {
    int e = blockIdx.x * 256 + threadIdx.x;
    if (e < E) {
        int s = ei[e];
        int d = ei[E + e];
        int pos = atomicAdd(&g_cursor[d], 1);
        g_csrc[pos] = s;
    }
}

// ---------------- M = Wq @ Wk^T  (64x64), SMEM-staged ----------------------------
__global__ void __launch_bounds__(1024) k_M(const float* __restrict__ Wq,
                                            const float* __restrict__ Wk) {
    __shared__ float sq[64 * 64];
    __shared__ float sk[64 * 64];
    int tid = threadIdx.x;
    for (int i = tid; i < 4096; i += 1024) { sq[i] = Wq[i]; sk[i] = Wk[i]; }
    __syncthreads();
    int idx = blockIdx.x * 1024 + tid;
    int d = idx >> 6, j = idx & 63;
    float acc = 0.f;
#pragma unroll
    for (int e = 0; e < 64; e++) acc = fmaf(sq[d * 64 + e], sk[j * 64 + e], acc);
    g_M[idx] = acc;
}

// ---------------- tall-skinny GEMM: g_T[n,64] = (A[n,K] @ W[K,64]) * dinv[row] ---
template <int K, int RPG>
__global__ void __launch_bounds__(256) k_gemm(const float* __restrict__ Aext,
                                              int srcLayer,
                                              const float* __restrict__ W,
                                              int nrows) {
    constexpr int ROWS = RPG * 16;
    __shared__ float shW[K * 64];
    __shared__ float shA[ROWS * K];
    int tid = threadIdx.x;

    const float* A = (srcLayer < 0) ? Aext : (g_H + (size_t)srcLayer * nrows * 64);

    {
        const float4* W4 = (const float4*)W;
        float4* sW4 = (float4*)shW;
        for (int i = tid; i < K * 16; i += 256) sW4[i] = W4[i];
    }
    int rowBase = blockIdx.x * ROWS;
    {
        float4* sA4 = (float4*)shA;
        const float4* A4 = (const float4*)A;
        const int q = K / 4;
        for (int i = tid; i < ROWS * q; i += 256) {
            int r = i / q;
            int row = rowBase + r;
            float4 v = make_float4(0.f, 0.f, 0.f, 0.f);
            if (row < nrows) v = A4[(size_t)row * q + (i - r * q)];
            sA4[i] = v;
        }
    }
    __syncthreads();

    int t = tid & 15, g = tid >> 4;
    float4 acc[RPG];
#pragma unroll
    for (int rr = 0; rr < RPG; rr++) acc[rr] = make_float4(0.f, 0.f, 0.f, 0.f);

#pragma unroll 4
    for (int k = 0; k < K; k += 4) {
        float4 w0 = *(const float4*)&shW[(k + 0) * 64 + t * 4];
        float4 w1 = *(const float4*)&shW[(k + 1) * 64 + t * 4];
        float4 w2 = *(const float4*)&shW[(k + 2) * 64 + t * 4];
        float4 w3 = *(const float4*)&shW[(k + 3) * 64 + t * 4];
#pragma unroll
        for (int rr = 0; rr < RPG; rr++) {
            float4 a4 = *(const float4*)&shA[(g * RPG + rr) * K + k];
            acc[rr].x = fmaf(a4.x, w0.x, acc[rr].x);
            acc[rr].y = fmaf(a4.x, w0.y, acc[rr].y);
            acc[rr].z = fmaf(a4.x, w0.z, acc[rr].z);
            acc[rr].w = fmaf(a4.x, w0.w, acc[rr].w);
            acc[rr].x = fmaf(a4.y, w1.x, acc[rr].x);
            acc[rr].y = fmaf(a4.y, w1.y, acc[rr].y);
            acc[rr].z = fmaf(a4.y, w1.z, acc[rr].z);
            acc[rr].w = fmaf(a4.y, w1.w, acc[rr].w);
            acc[rr].x = fmaf(a4.z, w2.x, acc[rr].x);
            acc[rr].y = fmaf(a4.z, w2.y, acc[rr].y);
            acc[rr].z = fmaf(a4.z, w2.z, acc[rr].z);
            acc[rr].w = fmaf(a4.z, w2.w, acc[rr].w);
            acc[rr].x = fmaf(a4.w, w3.x, acc[rr].x);
            acc[rr].y = fmaf(a4.w, w3.y, acc[rr].y);
            acc[rr].z = fmaf(a4.w, w3.z, acc[rr].z);
            acc[rr].w = fmaf(a4.w, w3.w, acc[rr].w);
        }
    }

#pragma unroll
    for (int rr = 0; rr < RPG; rr++) {
        int row = rowBase + g * RPG + rr;
        if (row < nrows) {
            float dv = g_dinv[row];
            float4 v = make_float4(acc[rr].x * dv, acc[rr].y * dv,
                                   acc[rr].z * dv, acc[rr].w * dv);
            ((float4*)g_T)[(size_t)row * 16 + t] = v;
        }
    }
}

// ---------------- scores as GEMM + fused dot: s[row] = (H[row] @ M) . H[row] -----
__global__ void __launch_bounds__(256) k_score(int nitems) {
    constexpr int K = 64, RPG = 4, ROWS = 64;
    __shared__ float shW[K * 64];
    __shared__ float shA[ROWS * K];
    int tid = threadIdx.x;

    {
        float4* sW4 = (float4*)shW;
        const float4* M4 = (const float4*)g_M;
        for (int i = tid; i < K * 16; i += 256) sW4[i] = M4[i];
    }
    int rowBase = blockIdx.x * ROWS;
    {
        float4* sA4 = (float4*)shA;
        const float4* A4 = (const float4*)g_H;
        for (int i = tid; i < ROWS * 16; i += 256) {
            int r = i >> 4;
            int row = rowBase + r;
            float4 v = make_float4(0.f, 0.f, 0.f, 0.f);
            if (row < nitems) v = A4[(size_t)row * 16 + (i & 15)];
            sA4[i] = v;
        }
    }
    __syncthreads();

    int t = tid & 15, g = tid >> 4;
    float4 acc[RPG];
#pragma unroll
    for (int rr = 0; rr < RPG; rr++) acc[rr] = make_float4(0.f, 0.f, 0.f, 0.f);

#pragma unroll 4
    for (int k = 0; k < K; k += 4) {
        float4 w0 = *(const float4*)&shW[(k + 0) * 64 + t * 4];
        float4 w1 = *(const float4*)&shW[(k + 1) * 64 + t * 4];
        float4 w2 = *(const float4*)&shW[(k + 2) * 64 + t * 4];
        float4 w3 = *(const float4*)&shW[(k + 3) * 64 + t * 4];
#pragma unroll
        for (int rr = 0; rr < RPG; rr++) {
            float4 a4 = *(const float4*)&shA[(g * RPG + rr) * K + k];
            acc[rr].x = fmaf(a4.x, w0.x, acc[rr].x);
            acc[rr].y = fmaf(a4.x, w0.y, acc[rr].y);
            acc[rr].z = fmaf(a4.x, w0.z, acc[rr].z);
            acc[rr].w = fmaf(a4.x, w0.w, acc[rr].w);
            acc[rr].x = fmaf(a4.y, w1.x, acc[rr].x);
            acc[rr].y = fmaf(a4.y, w1.y, acc[rr].y);
            acc[rr].z = fmaf(a4.y, w1.z, acc[rr].z);
            acc[rr].w = fmaf(a4.y, w1.w, acc[rr].w);
            acc[rr].x = fmaf(a4.z, w2.x, acc[rr].x);
            acc[rr].y = fmaf(a4.z, w2.y, acc[rr].y);
            acc[rr].z = fmaf(a4.z, w2.z, acc[rr].z);
            acc[rr].w = fmaf(a4.z, w2.w, acc[rr].w);
            acc[rr].x = fmaf(a4.w, w3.x, acc[rr].x);
            acc[rr].y = fmaf(a4.w, w3.y, acc[rr].y);
            acc[rr].z = fmaf(a4.w, w3.z, acc[rr].z);
            acc[rr].w = fmaf(a4.w, w3.w, acc[rr].w);
        }
    }

#pragma unroll
    for (int rr = 0; rr < RPG; rr++) {
        int row = rowBase + g * RPG + rr;
        float4 h4 = *(const float4*)&shA[(g * RPG + rr) * K + t * 4];
        float p = acc[rr].x * h4.x + acc[rr].y * h4.y
                + acc[rr].z * h4.z + acc[rr].w * h4.w;
        p += __shfl_xor_sync(0xffffffffu, p, 1);
        p += __shfl_xor_sync(0xffffffffu, p, 2);
        p += __shfl_xor_sync(0xffffffffu, p, 4);
        p += __shfl_xor_sync(0xffffffffu, p, 8);
        if (t == 0 && row < nitems) g_scores[row] = p * 10.0f;  // 1/TEMP
    }
}

// ---------------- CSR gather propagate + bias + relu, fused ----------------------
__global__ void __launch_bounds__(256) k_gather(int layer, const float* __restrict__ b,
                                                int n) {
    int warp = (blockIdx.x * 256 + threadIdx.x) >> 5;
    int lane = threadIdx.x & 31;
    if (warp >= n) return;
    int start = g_rowptr[warp];
    int end = g_rowptr[warp + 1];
    const float2* T2 = (const float2*)g_T;
    float2 a = T2[(size_t)warp * 32 + lane];      // Ts[d]
    int j = start;
    for (; j + 8 <= end; j += 8) {
        int s0 = g_csrc[j],     s1 = g_csrc[j + 1], s2 = g_csrc[j + 2], s3 = g_csrc[j + 3];
        int s4 = g_csrc[j + 4], s5 = g_csrc[j + 5], s6 = g_csrc[j + 6], s7 = g_csrc[j + 7];
        float2 v0 = T2[(size_t)s0 * 32 + lane];
        float2 v1 = T2[(size_t)s1 * 32 + lane];
        float2 v2 = T2[(size_t)s2 * 32 + lane];
        float2 v3 = T2[(size_t)s3 * 32 + lane];
        float2 v4 = T2[(size_t)s4 * 32 + lane];
        float2 v5 = T2[(size_t)s5 * 32 + lane];
        float2 v6 = T2[(size_t)s6 * 32 + lane];
        float2 v7 = T2[(size_t)s7 * 32 + lane];
        a.x += ((v0.x + v1.x) + (v2.x + v3.x)) + ((v4.x + v5.x) + (v6.x + v7.x));
        a.y += ((v0.y + v1.y) + (v2.y + v3.y)) + ((v4.y + v5.y) + (v6.y + v7.y));
    }
    for (; j < end; j++) {
        int s = g_csrc[j];
        float2 v = T2[(size_t)s * 32 + lane];
        a.x += v.x;
        a.y += v.y;
    }
    float dv = g_dinv[warp];
    float2 bb = ((const float2*)b)[lane];
    float2 h;
    h.x = fmaxf(fmaf(a.x, dv, bb.x), 0.f);
    h.y = fmaxf(fmaf(a.y, dv, bb.y), 0.f);
    ((float2*)g_H)[(size_t)layer * n * 32 + (size_t)warp * 32 + lane] = h;
}

// ---------------- fused softmax + weighted sum + output GEMM ---------------------
__global__ void __launch_bounds__(128) k_final(const float* __restrict__ Wout,
                                               const float* __restrict__ bout,
                                               float* __restrict__ out, int n) {
    __shared__ float shW[64 * 40];
    __shared__ float shB[40];
    __shared__ float shS[16][64];
    int tid = threadIdx.x;
    for (int i = tid; i < 64 * 40; i += 128) shW[i] = Wout[i];
    if (tid < 40) shB[tid] = bout[tid];

    int nodeBase = blockIdx.x * 16;
    int nl = tid >> 3;
    int dg = tid & 7;
    int node = nodeBase + nl;
    if (node < n) {
        float s0 = g_scores[node];
        float s1 = g_scores[n + node];
        float s2 = g_scores[2 * n + node];
        float s3 = g_scores[3 * n + node];
        float m = fmaxf(fmaxf(s0, s1), fmaxf(s2, s3));
        float e0 = __expf(s0 - m), e1 = __expf(s1 - m);
        float e2 = __expf(s2 - m), e3 = __expf(s3 - m);
        float inv = 1.0f / (e0 + e1 + e2 + e3);
        e0 *= inv; e1 *= inv; e2 *= inv; e3 *= inv;
        size_t nh = (size_t)n * 64;
        size_t off0 = (size_t)node * 64 + dg * 8;
#pragma unroll
        for (int dd = 0; dd < 8; dd++) {
            size_t o = off0 + dd;
            float v = e0 * g_H[o] + e1 * g_H[nh + o] + e2 * g_H[2 * nh + o] + e3 * g_H[3 * nh + o];
            shS[nl][dg * 8 + dd] = v;
        }
    }
    __syncthreads();

    for (int o = tid; o < 16 * 40; o += 128) {
        int n2 = o / 40, c = o - n2 * 40;
        int node2 = nodeBase + n2;
        if (node2 < n) {
            float acc = shB[c];
#pragma unroll
            for (int k = 0; k < 64; k++) acc = fmaf(shS[n2][k], shW[k * 40 + c], acc);
            out[(size_t)node2 * 40 + c] = acc;
        }
    }
}

// ---------------- launch ---------------------------------------------------------
extern "C" void kernel_launch(void* const* d_in, const int* in_sizes, int n_in,
                              void* d_out, int out_size) {
    const float* x    = (const float*)d_in[0];
    const int*   ei   = (const int*)d_in[1];   // int32 on device
    const float* W0   = (const float*)d_in[2];
    const float* b0   = (const float*)d_in[3];
    const float* Ws   = (const float*)d_in[4];
    const float* bs   = (const float*)d_in[5];
    const float* Wq   = (const float*)d_in[6];
    const float* Wk   = (const float*)d_in[7];
    const float* Wout = (const float*)d_in[8];
    const float* bout = (const float*)d_in[9];
    float* out        = (float*)d_out;

    int n = in_sizes[0] / 128;
    int E = in_sizes[1] / 2;
    int nparts = (n + SCAN_BLK - 1) / SCAN_BLK;

    // launch order arranged so launch #5 (ncu -s 5 -c 1) is the K=128 GEMM
    k_zerocnt<<<(n + 255) / 256, 256>>>(n);            // 0
    k_count<<<(E + 255) / 256, 256>>>(ei, E);          // 1
    k_scan1<<<nparts, 256>>>(n);                       // 2 (also writes dinv)
    k_scan2<<<1, MAX_PARTS>>>(nparts, n);              // 3
    k_scan3<<<nparts, 256>>>(n);                       // 4
    k_gemm<128, 4><<<(n + 63) / 64, 256>>>(x, -1, W0, n);   // 5  <- profiled
    k_fill<<<(E + 255) / 256, 256>>>(ei, E);           // 6
    k_M<<<4, 1024>>>(Wq, Wk);                          // 7

    int gatherBlocks = (n * 32 + 255) / 256;

    for (int l = 0; l < 4; l++) {
        if (l > 0) {
            k_gemm<64, 4><<<(n + 63) / 64, 256>>>(nullptr, l - 1,
                                                  Ws + (size_t)(l - 1) * 64 * 64, n);
        }
        const float* b = (l == 0) ? b0 : (bs + (size_t)(l - 1) * 64);
        k_gather<<<gatherBlocks, 256>>>(l, b, n);
    }

    int nitems = 4 * n;
    k_score<<<(nitems + 63) / 64, 256>>>(nitems);
    k_final<<<(n + 15) / 16, 128>>>(Wout, bout, out, n);
}

// round 10
// speedup vs baseline: 2.4758x; 1.0281x over previous
#include <cuda_runtime.h>
#include <cstdint>

#define NN 100000
#define EE 1600000
#define SCAN_BLK 2048          // elements per scan block (256 threads x 8)
#define MAX_PARTS 128

typedef unsigned long long u64;

// f32x2 packed helpers (sm_100+): bit-exact 2-wide fp32 FMA, 2x FFMA throughput
__device__ __forceinline__ u64 pk2(float x) {
    u64 r; asm("mov.b64 %0, {%1, %1};" : "=l"(r) : "f"(x)); return r;
}
__device__ __forceinline__ void fma2(u64& d, u64 a, u64 b) {
    asm("fma.rn.f32x2 %0, %1, %2, %0;" : "+l"(d) : "l"(a), "l"(b));
}
__device__ __forceinline__ void unpk2(u64 v, float& lo, float& hi) {
    asm("mov.b64 {%0, %1}, %2;" : "=f"(lo), "=f"(hi) : "l"(v));
}

// ---------------- scratch (device globals; no allocations allowed) -------------
__device__ int   g_cnt[NN];            // in-degree (edges only)
__device__ int   g_rowptr[NN + 1];     // CSR row pointers (by dst)
__device__ int   g_cursor[NN];         // fill cursors
__device__ int   g_csrc[EE];           // CSR src indices
__device__ int   g_part[MAX_PARTS];    // scan partials
__device__ float g_dinv[NN];
__device__ float g_T[NN * 64];         // Ts = (h @ W) * dinv[row]
__device__ float g_H[4 * NN * 64];     // per-layer post-relu features
__device__ float g_M[64 * 64];         // Wq @ Wk^T
__device__ float g_scores[4 * NN];

// ---------------- degree / CSR build --------------------------------------------
__global__ void k_zerocnt(int n) {
    int i = blockIdx.x * 256 + threadIdx.x;
    if (i < n) g_cnt[i] = 0;
}

__global__ void k_count(const int* __restrict__ ei, int E) {
    int e = blockIdx.x * 256 + threadIdx.x;
    if (e < E) atomicAdd(&g_cnt[ei[E + e]], 1);
}

// ---- scan phase 1: per-block reduce + dinv  -------------------------------------
__global__ void __launch_bounds__(256) k_scan1(int n) {
    int tid = threadIdx.x;
    int base = blockIdx.x * SCAN_BLK + tid * 8;
    int s = 0;
#pragma unroll
    for (int k = 0; k < 8; k++) {
        int i = base + k;
        if (i < n) {
            int c = g_cnt[i];
            s += c;
            g_dinv[i] = rsqrtf((float)(c + 1));   // +1 self loop
        }
    }
#pragma unroll
    for (int off = 16; off; off >>= 1) s += __shfl_xor_sync(0xffffffffu, s, off);
    __shared__ int sw[8];
    if ((tid & 31) == 0) sw[tid >> 5] = s;
    __syncthreads();
    if (tid == 0) {
        int t = 0;
#pragma unroll
        for (int w = 0; w < 8; w++) t += sw[w];
        g_part[blockIdx.x] = t;
    }
}

// ---- scan phase 2: exclusive scan of partials (single small block) --------------
__global__ void k_scan2(int nparts, int n) {
    __shared__ int sh[MAX_PARTS];
    int tid = threadIdx.x;
    sh[tid] = (tid < nparts) ? g_part[tid] : 0;
    __syncthreads();
    for (int off = 1; off < MAX_PARTS; off <<= 1) {
        int t = (tid >= off) ? sh[tid - off] : 0;
        __syncthreads();
        sh[tid] += t;
        __syncthreads();
    }
    if (tid < nparts) g_part[tid] = (tid ? sh[tid - 1] : 0);
    if (tid == MAX_PARTS - 1) g_rowptr[n] = sh[MAX_PARTS - 1];
}

// ---- scan phase 3: block-local exclusive scan + offset -> rowptr/cursor ---------
__global__ void __launch_bounds__(256) k_scan3(int n) {
    __shared__ int sw[8];
    int tid = threadIdx.x;
    int base = blockIdx.x * SCAN_BLK + tid * 8;
    int v[8];
    int s = 0;
#pragma unroll
    for (int k = 0; k < 8; k++) {
        int i = base + k;
        int c = (i < n) ? g_cnt[i] : 0;
        v[k] = s;          // exclusive within thread
        s += c;
    }
    int lane = tid & 31, w = tid >> 5;
    int incl = s;
#pragma unroll
    for (int off = 1; off < 32; off <<= 1) {
        int t = __shfl_up_sync(0xffffffffu, incl, off);
        if (lane >= off) incl += t;
    }
    if (lane == 31) sw[w] = incl;
    __syncthreads();
    int wofs = 0;
    if (tid < 8) {
        int t = sw[tid];
        int e = 0;
        for (int k = 0; k < 8; k++) { int tv = __shfl_sync(0xffu, t, k); if (k < tid) e += tv; }
        sw[tid] = e;
        (void)e;
    }
    __syncthreads();
    wofs = sw[w];
    int texcl = wofs + incl - s;                 // exclusive across block
    int blkofs = g_part[blockIdx.x];
#pragma unroll
    for (int k = 0; k < 8; k++) {
        int i = base + k;
        if (i < n) {
            int p = blkofs + texcl + v[k];
            g_rowptr[i] = p;
            g_cursor[i] = p;
        }
    }
}

__global__ void k_fill(const int* __restrict__ ei, int E) {
    int e = blockIdx.x * 256 + threadIdx.x;
    if (e < E) {
        int s = ei[e];
        int d = ei[E + e];
        int pos = atomicAdd(&g_cursor[d], 1);
        g_csrc[pos] = s;
    }
}

// ---------------- M = Wq @ Wk^T  (64x64), SMEM-staged ----------------------------
__global__ void __launch_bounds__(1024) k_M(const float* __restrict__ Wq,
                                            const float* __restrict__ Wk) {
    __shared__ float sq[64 * 64];
    __shared__ float sk[64 * 64];
    int tid = threadIdx.x;
    for (int i = tid; i < 4096; i += 1024) { sq[i] = Wq[i]; sk[i] = Wk[i]; }
    __syncthreads();
    int idx = blockIdx.x * 1024 + tid;
    int d = idx >> 6, j = idx & 63;
    float acc = 0.f;
#pragma unroll
    for (int e = 0; e < 64; e++) acc = fmaf(sq[d * 64 + e], sk[j * 64 + e], acc);
    g_M[idx] = acc;
}

// ---------------- tall-skinny GEMM (f32x2): g_T = (A @ W) * dinv[row] ------------
template <int K, int RPG>
__global__ void __launch_bounds__(256) k_gemm(const float* __restrict__ Aext,
                                              int srcLayer,
                                              const float* __restrict__ W,
                                              int nrows) {
    constexpr int ROWS = RPG * 16;
    __shared__ float shW[K * 64];
    __shared__ float shA[ROWS * K];
    int tid = threadIdx.x;

    const float* A = (srcLayer < 0) ? Aext : (g_H + (size_t)srcLayer * nrows * 64);

    {
        const float4* W4 = (const float4*)W;
        float4* sW4 = (float4*)shW;
        for (int i = tid; i < K * 16; i += 256) sW4[i] = W4[i];
    }
    int rowBase = blockIdx.x * ROWS;
    {
        float4* sA4 = (float4*)shA;
        const float4* A4 = (const float4*)A;
        const int q = K / 4;
        for (int i = tid; i < ROWS * q; i += 256) {
            int r = i / q;
            int row = rowBase + r;
            float4 v = make_float4(0.f, 0.f, 0.f, 0.f);
            if (row < nrows) v = A4[(size_t)row * q + (i - r * q)];
            sA4[i] = v;
        }
    }
    __syncthreads();

    int t = tid & 15, g = tid >> 4;
    u64 acc[RPG][2];
#pragma unroll
    for (int rr = 0; rr < RPG; rr++) { acc[rr][0] = 0ull; acc[rr][1] = 0ull; }

#pragma unroll 4
    for (int k = 0; k < K; k += 4) {
        ulonglong2 w0 = *(const ulonglong2*)&shW[(k + 0) * 64 + t * 4];
        ulonglong2 w1 = *(const ulonglong2*)&shW[(k + 1) * 64 + t * 4];
        ulonglong2 w2 = *(const ulonglong2*)&shW[(k + 2) * 64 + t * 4];
        ulonglong2 w3 = *(const ulonglong2*)&shW[(k + 3) * 64 + t * 4];
#pragma unroll
        for (int rr = 0; rr < RPG; rr++) {
            float4 a4 = *(const float4*)&shA[(g * RPG + rr) * K + k];
            u64 a0 = pk2(a4.x), a1 = pk2(a4.y), a2 = pk2(a4.z), a3 = pk2(a4.w);
            fma2(acc[rr][0], a0, w0.x); fma2(acc[rr][1], a0, w0.y);
            fma2(acc[rr][0], a1, w1.x); fma2(acc[rr][1], a1, w1.y);
            fma2(acc[rr][0], a2, w2.x); fma2(acc[rr][1], a2, w2.y);
            fma2(acc[rr][0], a3, w3.x); fma2(acc[rr][1], a3, w3.y);
        }
    }

#pragma unroll
    for (int rr = 0; rr < RPG; rr++) {
        int row = rowBase + g * RPG + rr;
        if (row < nrows) {
            float dv = g_dinv[row];
            float4 v;
            unpk2(acc[rr][0], v.x, v.y);
            unpk2(acc[rr][1], v.z, v.w);
            v.x *= dv; v.y *= dv; v.z *= dv; v.w *= dv;
            ((float4*)g_T)[(size_t)row * 16 + t] = v;
        }
    }
}

// ---------------- scores as GEMM (f32x2) + fused dot ------------------------------
__global__ void __launch_bounds__(256) k_score(int nitems) {
    constexpr int K = 64, RPG = 4, ROWS = 64;
    __shared__ float shW[K * 64];
    __shared__ float shA[ROWS * K];
    int tid = threadIdx.x;

    {
        float4* sW4 = (float4*)shW;
        const float4* M4 = (const float4*)g_M;
        for (int i = tid; i < K * 16; i += 256) sW4[i] = M4[i];
    }
    int rowBase = blockIdx.x * ROWS;
    {
        float4* sA4 = (float4*)shA;
        const float4* A4 = (const float4*)g_H;
        for (int i = tid; i < ROWS * 16; i += 256) {
            int r = i >> 4;
            int row = rowBase + r;
            float4 v = make_float4(0.f, 0.f, 0.f, 0.f);
            if (row < nitems) v = A4[(size_t)row * 16 + (i & 15)];
            sA4[i] = v;
        }
    }
    __syncthreads();

    int t = tid & 15, g = tid >> 4;
    u64 acc[RPG][2];
#pragma unroll
    for (int rr = 0; rr < RPG; rr++) { acc[rr][0] = 0ull; acc[rr][1] = 0ull; }

#pragma unroll 4
    for (int k = 0; k < K; k += 4) {
        ulonglong2 w0 = *(const ulonglong2*)&shW[(k + 0) * 64 + t * 4];
        ulonglong2 w1 = *(const ulonglong2*)&shW[(k + 1) * 64 + t * 4];
        ulonglong2 w2 = *(const ulonglong2*)&shW[(k + 2) * 64 + t * 4];
        ulonglong2 w3 = *(const ulonglong2*)&shW[(k + 3) * 64 + t * 4];
#pragma unroll
        for (int rr = 0; rr < RPG; rr++) {
            float4 a4 = *(const float4*)&shA[(g * RPG + rr) * K + k];
            u64 a0 = pk2(a4.x), a1 = pk2(a4.y), a2 = pk2(a4.z), a3 = pk2(a4.w);
            fma2(acc[rr][0], a0, w0.x); fma2(acc[rr][1], a0, w0.y);
            fma2(acc[rr][0], a1, w1.x); fma2(acc[rr][1], a1, w1.y);
            fma2(acc[rr][0], a2, w2.x); fma2(acc[rr][1], a2, w2.y);
            fma2(acc[rr][0], a3, w3.x); fma2(acc[rr][1], a3, w3.y);
        }
    }

#pragma unroll
    for (int rr = 0; rr < RPG; rr++) {
        int row = rowBase + g * RPG + rr;
        float4 h4 = *(const float4*)&shA[(g * RPG + rr) * K + t * 4];
        float4 pv;
        unpk2(acc[rr][0], pv.x, pv.y);
        unpk2(acc[rr][1], pv.z, pv.w);
        float p = pv.x * h4.x + pv.y * h4.y + pv.z * h4.z + pv.w * h4.w;
        p += __shfl_xor_sync(0xffffffffu, p, 1);
        p += __shfl_xor_sync(0xffffffffu, p, 2);
        p += __shfl_xor_sync(0xffffffffu, p, 4);
        p += __shfl_xor_sync(0xffffffffu, p, 8);
        if (t == 0 && row < nitems) g_scores[row] = p * 10.0f;  // 1/TEMP
    }
}

// ---------------- CSR gather propagate + bias + relu, fused ----------------------
__global__ void __launch_bounds__(256) k_gather(int layer, const float* __restrict__ b,
                                                int n) {
    int warp = (blockIdx.x * 256 + threadIdx.x) >> 5;
    int lane = threadIdx.x & 31;
    if (warp >= n) return;
    int start = g_rowptr[warp];
    int end = g_rowptr[warp + 1];
    const float2* T2 = (const float2*)g_T;
    float2 a = T2[(size_t)warp * 32 + lane];      // Ts[d]
    int j = start;
    for (; j + 8 <= end; j += 8) {
        int s0 = g_csrc[j],     s1 = g_csrc[j + 1], s2 = g_csrc[j + 2], s3 = g_csrc[j + 3];
        int s4 = g_csrc[j + 4], s5 = g_csrc[j + 5], s6 = g_csrc[j + 6], s7 = g_csrc[j + 7];
        float2 v0 = T2[(size_t)s0 * 32 + lane];
        float2 v1 = T2[(size_t)s1 * 32 + lane];
        float2 v2 = T2[(size_t)s2 * 32 + lane];
        float2 v3 = T2[(size_t)s3 * 32 + lane];
        float2 v4 = T2[(size_t)s4 * 32 + lane];
        float2 v5 = T2[(size_t)s5 * 32 + lane];
        float2 v6 = T2[(size_t)s6 * 32 + lane];
        float2 v7 = T2[(size_t)s7 * 32 + lane];
        a.x += ((v0.x + v1.x) + (v2.x + v3.x)) + ((v4.x + v5.x) + (v6.x + v7.x));
        a.y += ((v0.y + v1.y) + (v2.y + v3.y)) + ((v4.y + v5.y) + (v6.y + v7.y));
    }
    for (; j < end; j++) {
        int s = g_csrc[j];
        float2 v = T2[(size_t)s * 32 + lane];
        a.x += v.x;
        a.y += v.y;
    }
    float dv = g_dinv[warp];
    float2 bb = ((const float2*)b)[lane];
    float2 h;
    h.x = fmaxf(fmaf(a.x, dv, bb.x), 0.f);
    h.y = fmaxf(fmaf(a.y, dv, bb.y), 0.f);
    ((float2*)g_H)[(size_t)layer * n * 32 + (size_t)warp * 32 + lane] = h;
}

// ---------------- fused softmax + weighted sum + output GEMM ---------------------
__global__ void __launch_bounds__(128) k_final(const float* __restrict__ Wout,
                                               const float* __restrict__ bout,
                                               float* __restrict__ out, int n) {
    __shared__ float shW[64 * 40];
    __shared__ float shB[40];
    __shared__ float shS[16][64];
    int tid = threadIdx.x;
    for (int i = tid; i < 64 * 40; i += 128) shW[i] = Wout[i];
    if (tid < 40) shB[tid] = bout[tid];

    int nodeBase = blockIdx.x * 16;
    int nl = tid >> 3;
    int dg = tid & 7;
    int node = nodeBase + nl;
    if (node < n) {
        float s0 = g_scores[node];
        float s1 = g_scores[n + node];
        float s2 = g_scores[2 * n + node];
        float s3 = g_scores[3 * n + node];
        float m = fmaxf(fmaxf(s0, s1), fmaxf(s2, s3));
        float e0 = __expf(s0 - m), e1 = __expf(s1 - m);
        float e2 = __expf(s2 - m), e3 = __expf(s3 - m);
        float inv = 1.0f / (e0 + e1 + e2 + e3);
        e0 *= inv; e1 *= inv; e2 *= inv; e3 *= inv;
        size_t nh = (size_t)n * 64;
        size_t off0 = (size_t)node * 64 + dg * 8;
#pragma unroll
        for (int dd = 0; dd < 8; dd++) {
            size_t o = off0 + dd;
            float v = e0 * g_H[o] + e1 * g_H[nh + o] + e2 * g_H[2 * nh + o] + e3 * g_H[3 * nh + o];
            shS[nl][dg * 8 + dd] = v;
        }
    }
    __syncthreads();

    for (int o = tid; o < 16 * 40; o += 128) {
        int n2 = o / 40, c = o - n2 * 40;
        int node2 = nodeBase + n2;
        if (node2 < n) {
            float acc = shB[c];
#pragma unroll
            for (int k = 0; k < 64; k++) acc = fmaf(shS[n2][k], shW[k * 40 + c], acc);
            out[(size_t)node2 * 40 + c] = acc;
        }
    }
}

// ---------------- launch ---------------------------------------------------------
extern "C" void kernel_launch(void* const* d_in, const int* in_sizes, int n_in,
                              void* d_out, int out_size) {
    const float* x    = (const float*)d_in[0];
    const int*   ei   = (const int*)d_in[1];   // int32 on device
    const float* W0   = (const float*)d_in[2];
    const float* b0   = (const float*)d_in[3];
    const float* Ws   = (const float*)d_in[4];
    const float* bs   = (const float*)d_in[5];
    const float* Wq   = (const float*)d_in[6];
    const float* Wk   = (const float*)d_in[7];
    const float* Wout = (const float*)d_in[8];
    const float* bout = (const float*)d_in[9];
    float* out        = (float*)d_out;

    int n = in_sizes[0] / 128;
    int E = in_sizes[1] / 2;
    int nparts = (n + SCAN_BLK - 1) / SCAN_BLK;

    k_zerocnt<<<(n + 255) / 256, 256>>>(n);            // 0
    k_count<<<(E + 255) / 256, 256>>>(ei, E);          // 1
    k_scan1<<<nparts, 256>>>(n);                       // 2 (also writes dinv)
    k_scan2<<<1, MAX_PARTS>>>(nparts, n);              // 3
    k_scan3<<<nparts, 256>>>(n);                       // 4
    k_gemm<128, 4><<<(n + 63) / 64, 256>>>(x, -1, W0, n);   // 5
    k_fill<<<(E + 255) / 256, 256>>>(ei, E);           // 6
    k_M<<<4, 1024>>>(Wq, Wk);                          // 7

    int gatherBlocks = (n * 32 + 255) / 256;

    for (int l = 0; l < 4; l++) {
        if (l > 0) {
            k_gemm<64, 4><<<(n + 63) / 64, 256>>>(nullptr, l - 1,
                                                  Ws + (size_t)(l - 1) * 64 * 64, n);
        }
        const float* b = (l == 0) ? b0 : (bs + (size_t)(l - 1) * 64);
        k_gather<<<gatherBlocks, 256>>>(l, b, n);
    }

    int nitems = 4 * n;
    k_score<<<(nitems + 63) / 64, 256>>>(nitems);
    k_final<<<(n + 15) / 16, 128>>>(Wout, bout, out, n);
}